// round 10
// baseline (speedup 1.0000x reference)
#include <cuda_runtime.h>
#include <cuda_bf16.h>
#include <math.h>
#include <stdint.h>

#define BDIM 32
#define L1DIM 128
#define L2DIM 128
#define DDIM 300
#define KDIM 50
#define ROWS1 (BDIM * L1DIM)   // 4096
#define ROWS2 (BDIM * L2DIM)   // 4096
#define KPAD 320               // D padded: 5 chunks of 64 bf16
#define NPAD 15104             // 118*128 compact (k*300+e) rows for Wb'
#define TROW (KDIM * KPAD)     // 16000: t storage row (k*320+e)

// Scratch (__device__ globals; zero-initialized at module load; pad regions
// never written so they stay zero across graph replays)
__device__ __nv_bfloat16 g_th[(size_t)ROWS1 * TROW];     // 131 MB
__device__ __nv_bfloat16 g_tl[(size_t)ROWS1 * TROW];     // 131 MB
__device__ float g_btp[(size_t)BDIM * 6400 * 128];       // 104.9 MB
__device__ float g_p1d[ROWS1 * KDIM];
__device__ float g_p1g[ROWS1 * KDIM];
__device__ float g_p2d[ROWS2 * KDIM];
__device__ float g_p2g[ROWS2 * KDIM];
__device__ __nv_bfloat16 g_e1h[(size_t)ROWS1 * KPAD];
__device__ __nv_bfloat16 g_e1l[(size_t)ROWS1 * KPAD];
__device__ __nv_bfloat16 g_e2h[(size_t)ROWS2 * KPAD];
__device__ __nv_bfloat16 g_e2l[(size_t)ROWS2 * KPAD];
__device__ __nv_bfloat16 g_wbh[(size_t)NPAD * KPAD];     // Wb'[(k*300+e)][d] hi
__device__ __nv_bfloat16 g_wbl[(size_t)NPAD * KPAD];     // lo

// ---------------------------------------------------------------------------
// helpers (plain sm_80+ PTX)
// ---------------------------------------------------------------------------
__device__ __forceinline__ uint32_t smem_u32(const void* p) {
    uint32_t a;
    asm("{ .reg .u64 t; cvta.to.shared.u64 t, %1; cvt.u32.u64 %0, t; }" : "=r"(a) : "l"(p));
    return a;
}
__device__ __forceinline__ void cpasync16(uint32_t dst, const void* src) {
    asm volatile("cp.async.cg.shared.global [%0], [%1], 16;" :: "r"(dst), "l"(src));
}
__device__ __forceinline__ void ldsm_x4(uint32_t& r0, uint32_t& r1, uint32_t& r2,
                                        uint32_t& r3, uint32_t addr) {
    asm volatile("ldmatrix.sync.aligned.m8n8.x4.shared.b16 {%0,%1,%2,%3}, [%4];"
                 : "=r"(r0), "=r"(r1), "=r"(r2), "=r"(r3) : "r"(addr));
}
__device__ __forceinline__ void mma_bf16(float* c, const uint32_t* a, const uint32_t* b) {
    asm volatile(
        "mma.sync.aligned.m16n8k16.row.col.f32.bf16.bf16.f32 "
        "{%0,%1,%2,%3}, {%4,%5,%6,%7}, {%8,%9}, {%0,%1,%2,%3};"
        : "+f"(c[0]), "+f"(c[1]), "+f"(c[2]), "+f"(c[3])
        : "r"(a[0]), "r"(a[1]), "r"(a[2]), "r"(a[3]), "r"(b[0]), "r"(b[1]));
}
__device__ __forceinline__ float tanh_hw(float x) {
    float y;
    asm("tanh.approx.f32 %0, %1;" : "=f"(y) : "f"(x));
    return y;
}

// ---------------------------------------------------------------------------
// conversion: e1/e2 fp32 -> bf16 hi/lo (padded to 320 with zeros)
// ---------------------------------------------------------------------------
__global__ void convA_kernel(const float* __restrict__ e1,
                             const float* __restrict__ e2) {
    int m = blockIdx.x;
    int d = threadIdx.x;                 // 0..319
    bool s2 = (m >= ROWS1);
    int row = s2 ? m - ROWS1 : m;
    const float* src = s2 ? e2 : e1;
    float v = (d < DDIM) ? src[(size_t)row * DDIM + d] : 0.f;
    __nv_bfloat16 hi = __float2bfloat16(v);
    __nv_bfloat16 lo = __float2bfloat16(v - __bfloat162float(hi));
    if (s2) { g_e2h[(size_t)row * KPAD + d] = hi; g_e2l[(size_t)row * KPAD + d] = lo; }
    else    { g_e1h[(size_t)row * KPAD + d] = hi; g_e1l[(size_t)row * KPAD + d] = lo; }
}

// Wb[k][d][e] -> Wb'[(k*300+e)][d]  (compact rows, transposed per k, split)
__global__ void convB_kernel(const float* __restrict__ Wb) {
    __shared__ float tile[32][33];
    int k  = blockIdx.z;
    int d0 = blockIdx.x * 32;
    int e0 = blockIdx.y * 32;
    int tx = threadIdx.x, ty = threadIdx.y;   // 32 x 8
    #pragma unroll
    for (int q = 0; q < 4; q++) {
        int d = d0 + ty + 8 * q;
        int e = e0 + tx;
        float v = 0.f;
        if (d < DDIM && e < DDIM)
            v = Wb[(size_t)k * DDIM * DDIM + (size_t)d * DDIM + e];
        tile[ty + 8 * q][tx] = v;
    }
    __syncthreads();
    #pragma unroll
    for (int q = 0; q < 4; q++) {
        int e = e0 + ty + 8 * q;
        int d = d0 + tx;
        if (e < DDIM) {
            float v = tile[tx][ty + 8 * q];
            __nv_bfloat16 hi = __float2bfloat16(v);
            __nv_bfloat16 lo = __float2bfloat16(v - __bfloat162float(hi));
            size_t o = (size_t)(k * DDIM + e) * KPAD + d;
            g_wbh[o] = hi;
            g_wbl[o] = lo;
        }
    }
}

// ---------------------------------------------------------------------------
// GEMM core (round-6 proven geometry): CTA 128x128, 8 warps as 4(m) x 2(n)
// -> warp tile 32x64, KC=64, 2-stage cp.async, 147 KB smem, 1 CTA/SM.
// ---------------------------------------------------------------------------
#define MM_THREADS 256
#define MM_KC 64
#define MM_ROWB 144                       // 64 bf16 (128B) + 16B pad
#define TILE_B (128 * MM_ROWB)            // 18432 per matrix
#define STAGE_B (4 * TILE_B)              // Ah, Al, Bh, Bl = 73728
#define MM_SMEM (2 * STAGE_B)             // 147456
#define NCHUNK (KPAD / MM_KC)             // 5

struct GemmCore {
    uint32_t sb;
    int tid, lane, wm, wn;
    const __nv_bfloat16 *aH, *aL, *bH, *bL;
    float acc[2][8][4];

    __device__ __forceinline__ void init(uint32_t sb_, int tid_,
                                         const __nv_bfloat16* aH_, const __nv_bfloat16* aL_,
                                         const __nv_bfloat16* bH_, const __nv_bfloat16* bL_) {
        sb = sb_; tid = tid_;
        lane = tid & 31;
        int w = tid >> 5;
        wm = (w >> 1) * 32;               // 0,32,64,96
        wn = (w & 1) * 64;                // 0,64
        aH = aH_; aL = aL_; bH = bH_; bL = bL_;
        #pragma unroll
        for (int mt = 0; mt < 2; mt++)
            #pragma unroll
            for (int nt = 0; nt < 8; nt++)
                #pragma unroll
                for (int q = 0; q < 4; q++) acc[mt][nt][q] = 0.f;
    }

    __device__ __forceinline__ void issue(int c) {
        int d0 = c * MM_KC;
        uint32_t stage = sb + (c & 1) * STAGE_B;
        #pragma unroll
        for (int it = 0; it < 16; it++) {
            int i = tid + MM_THREADS * it;        // 0..4095
            int mat = i >> 10;                     // Ah, Al, Bh, Bl
            int idx = i & 1023;
            int r = idx >> 3, c4 = idx & 7;        // 128 rows x 8 float4
            const __nv_bfloat16* src;
            if (mat == 0)      src = aH;
            else if (mat == 1) src = aL;
            else if (mat == 2) src = bH;
            else               src = bL;
            src += (size_t)r * KPAD + d0 + c4 * 8;
            cpasync16(stage + mat * TILE_B + r * MM_ROWB + c4 * 16, src);
        }
        asm volatile("cp.async.commit_group;" ::: "memory");
    }

    __device__ __forceinline__ void compute(int c) {
        uint32_t sA_h = sb + (c & 1) * STAGE_B;
        uint32_t sA_l = sA_h + TILE_B;
        uint32_t sB_h = sA_h + 2 * TILE_B;
        uint32_t sB_l = sA_h + 3 * TILE_B;
        #pragma unroll
        for (int kk = 0; kk < MM_KC / 16; kk++) {
            uint32_t ah[2][4], al[2][4];
            #pragma unroll
            for (int mt = 0; mt < 2; mt++) {
                uint32_t aoff = (uint32_t)(wm + mt * 16 + (lane & 15)) * MM_ROWB
                              + kk * 32 + (lane >> 4) * 16;
                ldsm_x4(ah[mt][0], ah[mt][1], ah[mt][2], ah[mt][3], sA_h + aoff);
                ldsm_x4(al[mt][0], al[mt][1], al[mt][2], al[mt][3], sA_l + aoff);
            }
            uint32_t bh[8][2], bl[8][2];
            #pragma unroll
            for (int nq = 0; nq < 4; nq++) {
                uint32_t brow = (uint32_t)(wn + nq * 16 + (lane & 7) + ((lane >> 4) << 3));
                uint32_t boff = brow * MM_ROWB + kk * 32 + ((lane >> 3) & 1) * 16;
                ldsm_x4(bh[2*nq][0], bh[2*nq][1], bh[2*nq+1][0], bh[2*nq+1][1], sB_h + boff);
                ldsm_x4(bl[2*nq][0], bl[2*nq][1], bl[2*nq+1][0], bl[2*nq+1][1], sB_l + boff);
            }
            #pragma unroll
            for (int mt = 0; mt < 2; mt++)
                #pragma unroll
                for (int nt = 0; nt < 8; nt++) {
                    mma_bf16(acc[mt][nt], ah[mt], bh[nt]);   // hi*hi
                    mma_bf16(acc[mt][nt], ah[mt], bl[nt]);   // hi*lo
                    mma_bf16(acc[mt][nt], al[mt], bh[nt]);   // lo*hi
                }
        }
    }

    __device__ __forceinline__ void run() {
        issue(0);
        issue(1);
        for (int c = 0; c < NCHUNK; c++) {
            if (c + 1 < NCHUNK) {
                asm volatile("cp.async.wait_group 1;" ::: "memory");
            } else {
                asm volatile("cp.async.wait_group 0;" ::: "memory");
            }
            __syncthreads();
            compute(c);
            __syncthreads();
            if (c + 2 < NCHUNK) issue(c + 2);
        }
    }
};

// ---------------------------------------------------------------------------
// Stage-1: t = e1[4096 x 320] @ Wb'[15104 x 320]^T
// epilogue: constant-div col -> (k,e), bf16 hi/lo into k*320+e layout
// ---------------------------------------------------------------------------
__global__ __launch_bounds__(MM_THREADS, 1)
void tmat_mma_kernel() {
    extern __shared__ char smem[];
    GemmCore g;
    int m0 = blockIdx.x * 128;
    int n0 = blockIdx.y * 128;
    g.init(smem_u32(smem), threadIdx.x,
           g_e1h + (size_t)m0 * KPAD, g_e1l + (size_t)m0 * KPAD,
           g_wbh + (size_t)n0 * KPAD, g_wbl + (size_t)n0 * KPAD);
    g.run();

    #pragma unroll
    for (int mt = 0; mt < 2; mt++) {
        int row = m0 + g.wm + mt * 16 + (g.lane >> 2);
        #pragma unroll
        for (int nt = 0; nt < 8; nt++) {
            int col = n0 + g.wn + nt * 8 + 2 * (g.lane & 3);
            if (col < KDIM * DDIM) {
                int k = col / DDIM;          // constant divisor -> mul-shift
                int e = col - k * DDIM;      // even, so pair stays inside k
                size_t off = (size_t)row * TROW + k * KPAD + e;
                #pragma unroll
                for (int rr = 0; rr < 2; rr++) {
                    float c0 = g.acc[mt][nt][2 * rr];
                    float c1 = g.acc[mt][nt][2 * rr + 1];
                    __nv_bfloat16 h0 = __float2bfloat16(c0);
                    __nv_bfloat16 h1 = __float2bfloat16(c1);
                    __nv_bfloat16 l0 = __float2bfloat16(c0 - __bfloat162float(h0));
                    __nv_bfloat16 l1 = __float2bfloat16(c1 - __bfloat162float(h1));
                    size_t o = off + (size_t)rr * 8 * TROW;
                    *reinterpret_cast<__nv_bfloat162*>(&g_th[o]) = __nv_bfloat162(h0, h1);
                    *reinterpret_cast<__nv_bfloat162*>(&g_tl[o]) = __nv_bfloat162(l0, l1);
                }
            }
        }
    }
}

// ---------------------------------------------------------------------------
// Stage-2 (per b): btp[6400 x 128] = T_b[6400 x 320] @ e2_b[128 x 320]^T
// ---------------------------------------------------------------------------
__global__ __launch_bounds__(MM_THREADS, 1)
void btp_mma_kernel() {
    extern __shared__ char smem[];
    GemmCore g;
    int m0 = blockIdx.x * 128;           // in 6400
    int b  = blockIdx.y;
    size_t abase = (size_t)b * 128 * TROW + (size_t)m0 * KPAD;
    g.init(smem_u32(smem), threadIdx.x,
           g_th + abase, g_tl + abase,
           g_e2h + (size_t)b * 128 * KPAD,
           g_e2l + (size_t)b * 128 * KPAD);
    g.run();

    float* dst = g_btp + (size_t)b * 6400 * 128;
    #pragma unroll
    for (int mt = 0; mt < 2; mt++) {
        int row = m0 + g.wm + mt * 16 + (g.lane >> 2);
        float* r0p = dst + (size_t)row * 128 + g.wn;
        float* r1p = r0p + 8 * 128;
        #pragma unroll
        for (int nt = 0; nt < 8; nt++) {
            int coff = nt * 8 + 2 * (g.lane & 3);
            *reinterpret_cast<float2*>(r0p + coff) = make_float2(g.acc[mt][nt][0], g.acc[mt][nt][1]);
            *reinterpret_cast<float2*>(r1p + coff) = make_float2(g.acc[mt][nt][2], g.acc[mt][nt][3]);
        }
    }
}

// ---------------------------------------------------------------------------
// gate epilogue: out[b,i,j] = sum_k u_k*( g*btp + (1-g)*tanh(sd) + bb_k )
// ---------------------------------------------------------------------------
#define G_P2LD 129
#define G_SMEM ((2 * KDIM * G_P2LD + 5 * 64) * 4)

__global__ __launch_bounds__(128)
void gate_kernel(const float* __restrict__ bg,
                 const float* __restrict__ bb,
                 const float* __restrict__ u,
                 float* __restrict__ out) {
    extern __shared__ float sm[];
    float* p2dS = sm;
    float* p2gS = sm + KDIM * G_P2LD;
    float* p1dS = p2gS + KDIM * G_P2LD;
    float* p1gS = p1dS + 64;
    float* uS   = p1gS + 64;
    float* bgS  = uS + 64;
    float* bbS  = bgS + 64;

    int blk = blockIdx.x;                 // b*128 + i
    int b   = blk >> 7;
    int tid = threadIdx.x;                // j

    const float* p2d_b = g_p2d + (size_t)b * 128 * KDIM;
    const float* p2g_b = g_p2g + (size_t)b * 128 * KDIM;
    for (int idx = tid; idx < 128 * KDIM; idx += 128) {
        int j = idx / KDIM, k = idx - j * KDIM;
        p2dS[k * G_P2LD + j] = p2d_b[idx];
        p2gS[k * G_P2LD + j] = p2g_b[idx];
    }
    if (tid < KDIM) {
        p1dS[tid] = g_p1d[(size_t)blk * KDIM + tid];
        p1gS[tid] = g_p1g[(size_t)blk * KDIM + tid];
        uS[tid]   = u[tid];
        bgS[tid]  = bg[tid];
        bbS[tid]  = bb[tid];
    }
    __syncthreads();

    const float* btp_row = g_btp + (size_t)b * 6400 * 128 + (size_t)(blk & 127) * KDIM * 128;

    float acc = 0.f;
    #pragma unroll 5
    for (int k = 0; k < KDIM; k++) {
        float btp = btp_row[k * 128 + tid];
        float sd  = p1dS[k] + p2dS[k * G_P2LD + tid];
        float sg  = p1gS[k] + p2gS[k * G_P2LD + tid] + bgS[k];
        float e   = __expf(-sg);
        float g   = __fdividef(1.f, 1.f + e);
        float sln = tanh_hw(sd);
        float mix = fmaf(g, btp - sln, sln) + bbS[k];
        acc = fmaf(uS[k], mix, acc);
    }
    out[(size_t)blk * 128 + tid] = acc;
}

// ---------------------------------------------------------------------------
// projections v2: warp = one 4-row group, lanes = consecutive k.
// ---------------------------------------------------------------------------
#define P_ROWS 32
#define P_THREADS 512
#define P_SMEM ((DDIM * KDIM + DDIM * P_ROWS) * 4)

__global__ __launch_bounds__(P_THREADS)
void proj_kernel(const float* __restrict__ e1,
                 const float* __restrict__ e2,
                 const float* __restrict__ Wd,
                 const float* __restrict__ Wg) {
    extern __shared__ float sm[];
    float* WS   = sm;                    // [300][50]
    float* rowS = sm + DDIM * KDIM;      // [300][32]

    int blk = blockIdx.x;
    int rt  = blk & 127;
    int mt  = (blk >> 7) & 1;
    int s   = blk >> 8;
    int row0 = rt * P_ROWS;
    int tid = threadIdx.x;

    const float* E = s ? e2 : e1;
    const float* W = (mt ? Wg : Wd) + s * DDIM * KDIM;
    float* out = s ? (mt ? g_p2g : g_p2d) : (mt ? g_p1g : g_p1d);

    const float4* W4 = reinterpret_cast<const float4*>(W);
    float4* WS4 = reinterpret_cast<float4*>(WS);
    for (int i = tid; i < DDIM * KDIM / 4; i += P_THREADS) WS4[i] = W4[i];

    for (int i = tid; i < P_ROWS * (DDIM / 4); i += P_THREADS) {
        int r = i / (DDIM / 4);
        int c4 = i % (DDIM / 4);
        float4 v = *reinterpret_cast<const float4*>(&E[(size_t)(row0 + r) * DDIM + 4 * c4]);
        rowS[(4 * c4 + 0) * P_ROWS + r] = v.x;
        rowS[(4 * c4 + 1) * P_ROWS + r] = v.y;
        rowS[(4 * c4 + 2) * P_ROWS + r] = v.z;
        rowS[(4 * c4 + 3) * P_ROWS + r] = v.w;
    }
    __syncthreads();

    int k  = tid & 63;
    int r4 = tid >> 6;                   // 0..7
    if (k < KDIM) {
        float4 acc = make_float4(0.f, 0.f, 0.f, 0.f);
        #pragma unroll 4
        for (int d = 0; d < DDIM; d++) {
            float4 x = *reinterpret_cast<const float4*>(&rowS[d * P_ROWS + r4 * 4]);
            float w = WS[d * KDIM + k];
            acc.x = fmaf(x.x, w, acc.x);
            acc.y = fmaf(x.y, w, acc.y);
            acc.z = fmaf(x.z, w, acc.z);
            acc.w = fmaf(x.w, w, acc.w);
        }
        int rb = row0 + r4 * 4;
        out[(size_t)(rb + 0) * KDIM + k] = acc.x;
        out[(size_t)(rb + 1) * KDIM + k] = acc.y;
        out[(size_t)(rb + 2) * KDIM + k] = acc.z;
        out[(size_t)(rb + 3) * KDIM + k] = acc.w;
    }
}

// ---------------------------------------------------------------------------
extern "C" void kernel_launch(void* const* d_in, const int* in_sizes, int n_in,
                              void* d_out, int out_size) {
    const float* e1 = (const float*)d_in[0];
    const float* e2 = (const float*)d_in[1];
    const float* Wb = (const float*)d_in[2];
    const float* Wd = (const float*)d_in[3];
    const float* Wg = (const float*)d_in[4];
    const float* bg = (const float*)d_in[5];
    const float* bb = (const float*)d_in[6];
    const float* u  = (const float*)d_in[7];
    float* out = (float*)d_out;

    cudaFuncSetAttribute(proj_kernel, cudaFuncAttributeMaxDynamicSharedMemorySize, P_SMEM);
    cudaFuncSetAttribute(tmat_mma_kernel, cudaFuncAttributeMaxDynamicSharedMemorySize, MM_SMEM);
    cudaFuncSetAttribute(btp_mma_kernel, cudaFuncAttributeMaxDynamicSharedMemorySize, MM_SMEM);
    cudaFuncSetAttribute(gate_kernel, cudaFuncAttributeMaxDynamicSharedMemorySize, G_SMEM);

    convA_kernel<<<2 * ROWS1, KPAD>>>(e1, e2);
    convB_kernel<<<dim3(10, 10, KDIM), dim3(32, 8)>>>(Wb);
    proj_kernel<<<512, P_THREADS, P_SMEM>>>(e1, e2, Wd, Wg);
    tmat_mma_kernel<<<dim3(ROWS1 / 128, NPAD / 128), MM_THREADS, MM_SMEM>>>();
    btp_mma_kernel<<<dim3(6400 / 128, BDIM), MM_THREADS, MM_SMEM>>>();
    gate_kernel<<<ROWS1, 128, G_SMEM>>>(bg, bb, u, out);
}

// round 11
// speedup vs baseline: 1.2019x; 1.2019x over previous
#include <cuda_runtime.h>
#include <cuda_bf16.h>
#include <math.h>
#include <stdint.h>

#define BDIM 32
#define L1DIM 128
#define L2DIM 128
#define DDIM 300
#define KDIM 50
#define ROWS1 (BDIM * L1DIM)   // 4096
#define ROWS2 (BDIM * L2DIM)   // 4096
#define KPAD 320               // D padded: 5 chunks of 64 bf16
#define NPAD 15104             // 118*128 compact (k*300+e) rows for Wb'
#define TSTRIDE (KDIM * DDIM)  // 15000

// Scratch (__device__ globals; zero-initialized at module load; pad regions
// never written so they stay zero across graph replays)
__device__ float g_t[(size_t)ROWS1 * TSTRIDE];           // 245.8 MB fp32 t
__device__ float g_btp[(size_t)BDIM * 6400 * 128];       // 104.9 MB
__device__ float g_p1d[ROWS1 * KDIM];
__device__ float g_p1g[ROWS1 * KDIM];
__device__ float g_p2d[ROWS2 * KDIM];
__device__ float g_p2g[ROWS2 * KDIM];
__device__ __nv_bfloat16 g_e1h[(size_t)ROWS1 * KPAD];
__device__ __nv_bfloat16 g_e1l[(size_t)ROWS1 * KPAD];
__device__ __nv_bfloat16 g_wbh[(size_t)NPAD * KPAD];     // Wb'[(k*300+e)][d] hi
__device__ __nv_bfloat16 g_wbl[(size_t)NPAD * KPAD];     // lo

// ---------------------------------------------------------------------------
// helpers (plain sm_80+ PTX)
// ---------------------------------------------------------------------------
__device__ __forceinline__ uint32_t smem_u32(const void* p) {
    uint32_t a;
    asm("{ .reg .u64 t; cvta.to.shared.u64 t, %1; cvt.u32.u64 %0, t; }" : "=r"(a) : "l"(p));
    return a;
}
__device__ __forceinline__ void cpasync16(uint32_t dst, const void* src) {
    asm volatile("cp.async.cg.shared.global [%0], [%1], 16;" :: "r"(dst), "l"(src));
}
__device__ __forceinline__ void cpasync16z(uint32_t dst, const void* src, int nb) {
    asm volatile("cp.async.cg.shared.global [%0], [%1], 16, %2;"
                 :: "r"(dst), "l"(src), "r"(nb));
}
__device__ __forceinline__ void ldsm_x4(uint32_t& r0, uint32_t& r1, uint32_t& r2,
                                        uint32_t& r3, uint32_t addr) {
    asm volatile("ldmatrix.sync.aligned.m8n8.x4.shared.b16 {%0,%1,%2,%3}, [%4];"
                 : "=r"(r0), "=r"(r1), "=r"(r2), "=r"(r3) : "r"(addr));
}
__device__ __forceinline__ void mma_bf16(float* c, const uint32_t* a, const uint32_t* b) {
    asm volatile(
        "mma.sync.aligned.m16n8k16.row.col.f32.bf16.bf16.f32 "
        "{%0,%1,%2,%3}, {%4,%5,%6,%7}, {%8,%9}, {%0,%1,%2,%3};"
        : "+f"(c[0]), "+f"(c[1]), "+f"(c[2]), "+f"(c[3])
        : "r"(a[0]), "r"(a[1]), "r"(a[2]), "r"(a[3]), "r"(b[0]), "r"(b[1]));
}
__device__ __forceinline__ void mma_tf32(float* c, const uint32_t* a, const uint32_t* b) {
    asm volatile(
        "mma.sync.aligned.m16n8k8.row.col.f32.tf32.tf32.f32 "
        "{%0,%1,%2,%3}, {%4,%5,%6,%7}, {%8,%9}, {%0,%1,%2,%3};"
        : "+f"(c[0]), "+f"(c[1]), "+f"(c[2]), "+f"(c[3])
        : "r"(a[0]), "r"(a[1]), "r"(a[2]), "r"(a[3]), "r"(b[0]), "r"(b[1]));
}
__device__ __forceinline__ float lds_f32(uint32_t a) {
    float v;
    asm volatile("ld.shared.f32 %0, [%1];" : "=f"(v) : "r"(a));
    return v;
}
__device__ __forceinline__ uint32_t f2tf32(float f) {
    uint32_t r;
    asm("cvt.rna.tf32.f32 %0, %1;" : "=r"(r) : "f"(f));
    return r;
}
__device__ __forceinline__ float tanh_hw(float x) {
    float y;
    asm("tanh.approx.f32 %0, %1;" : "=f"(y) : "f"(x));
    return y;
}

// ---------------------------------------------------------------------------
// conversion: e1 fp32 -> bf16 hi/lo (padded to 320 with zeros)
// ---------------------------------------------------------------------------
__global__ void convA_kernel(const float* __restrict__ e1) {
    int m = blockIdx.x;
    int d = threadIdx.x;                 // 0..319
    float v = (d < DDIM) ? e1[(size_t)m * DDIM + d] : 0.f;
    __nv_bfloat16 hi = __float2bfloat16(v);
    __nv_bfloat16 lo = __float2bfloat16(v - __bfloat162float(hi));
    g_e1h[(size_t)m * KPAD + d] = hi;
    g_e1l[(size_t)m * KPAD + d] = lo;
}

// Wb[k][d][e] -> Wb'[(k*300+e)][d]  (compact rows, transposed per k, split)
__global__ void convB_kernel(const float* __restrict__ Wb) {
    __shared__ float tile[32][33];
    int k  = blockIdx.z;
    int d0 = blockIdx.x * 32;
    int e0 = blockIdx.y * 32;
    int tx = threadIdx.x, ty = threadIdx.y;   // 32 x 8
    #pragma unroll
    for (int q = 0; q < 4; q++) {
        int d = d0 + ty + 8 * q;
        int e = e0 + tx;
        float v = 0.f;
        if (d < DDIM && e < DDIM)
            v = Wb[(size_t)k * DDIM * DDIM + (size_t)d * DDIM + e];
        tile[ty + 8 * q][tx] = v;
    }
    __syncthreads();
    #pragma unroll
    for (int q = 0; q < 4; q++) {
        int e = e0 + ty + 8 * q;
        int d = d0 + tx;
        if (e < DDIM) {
            float v = tile[tx][ty + 8 * q];
            __nv_bfloat16 hi = __float2bfloat16(v);
            __nv_bfloat16 lo = __float2bfloat16(v - __bfloat162float(hi));
            size_t o = (size_t)(k * DDIM + e) * KPAD + d;
            g_wbh[o] = hi;
            g_wbl[o] = lo;
        }
    }
}

// ---------------------------------------------------------------------------
// Stage-1 GEMM (round-6 verbatim): CTA 128x128, 8 warps 4(m)x2(n) -> warp
// 32x64, KC=64, 2-stage cp.async, 147 KB smem, fp32 epilogue into g_t.
// ---------------------------------------------------------------------------
#define MM_THREADS 256
#define MM_KC 64
#define MM_ROWB 144                       // 64 bf16 (128B) + 16B pad
#define TILE_B (128 * MM_ROWB)            // 18432 per matrix
#define STAGE_B (4 * TILE_B)              // Ah, Al, Bh, Bl = 73728
#define MM_SMEM (2 * STAGE_B)             // 147456
#define NCHUNK (KPAD / MM_KC)             // 5

__global__ __launch_bounds__(MM_THREADS, 1)
void tmat_mma_kernel() {
    extern __shared__ char smem[];
    uint32_t sb = smem_u32(smem);
    int tid  = threadIdx.x;
    int lane = tid & 31;
    int w    = tid >> 5;
    int wm   = (w >> 1) * 32;
    int wn   = (w & 1) * 64;
    int m0 = blockIdx.x * 128;
    int n0 = blockIdx.y * 128;

    const __nv_bfloat16* aH = g_e1h + (size_t)m0 * KPAD;
    const __nv_bfloat16* aL = g_e1l + (size_t)m0 * KPAD;
    const __nv_bfloat16* bH = g_wbh + (size_t)n0 * KPAD;
    const __nv_bfloat16* bL = g_wbl + (size_t)n0 * KPAD;

    float acc[2][8][4];
    #pragma unroll
    for (int mt = 0; mt < 2; mt++)
        #pragma unroll
        for (int nt = 0; nt < 8; nt++)
            #pragma unroll
            for (int q = 0; q < 4; q++) acc[mt][nt][q] = 0.f;

    auto issue = [&](int c) {
        int d0 = c * MM_KC;
        uint32_t stage = sb + (c & 1) * STAGE_B;
        #pragma unroll
        for (int it = 0; it < 16; it++) {
            int i = tid + MM_THREADS * it;        // 0..4095
            int mat = i >> 10;                     // Ah, Al, Bh, Bl
            int idx = i & 1023;
            int r = idx >> 3, c4 = idx & 7;
            const __nv_bfloat16* src;
            if (mat == 0)      src = aH;
            else if (mat == 1) src = aL;
            else if (mat == 2) src = bH;
            else               src = bL;
            src += (size_t)r * KPAD + d0 + c4 * 8;
            cpasync16(stage + mat * TILE_B + r * MM_ROWB + c4 * 16, src);
        }
        asm volatile("cp.async.commit_group;" ::: "memory");
    };

    issue(0);
    issue(1);

    for (int c = 0; c < NCHUNK; c++) {
        if (c + 1 < NCHUNK) {
            asm volatile("cp.async.wait_group 1;" ::: "memory");
        } else {
            asm volatile("cp.async.wait_group 0;" ::: "memory");
        }
        __syncthreads();

        uint32_t sA_h = sb + (c & 1) * STAGE_B;
        uint32_t sA_l = sA_h + TILE_B;
        uint32_t sB_h = sA_h + 2 * TILE_B;
        uint32_t sB_l = sA_h + 3 * TILE_B;
        #pragma unroll
        for (int kk = 0; kk < MM_KC / 16; kk++) {
            uint32_t ah[2][4], al[2][4];
            #pragma unroll
            for (int mt = 0; mt < 2; mt++) {
                uint32_t aoff = (uint32_t)(wm + mt * 16 + (lane & 15)) * MM_ROWB
                              + kk * 32 + (lane >> 4) * 16;
                ldsm_x4(ah[mt][0], ah[mt][1], ah[mt][2], ah[mt][3], sA_h + aoff);
                ldsm_x4(al[mt][0], al[mt][1], al[mt][2], al[mt][3], sA_l + aoff);
            }
            uint32_t bh[8][2], bl[8][2];
            #pragma unroll
            for (int nq = 0; nq < 4; nq++) {
                uint32_t brow = (uint32_t)(wn + nq * 16 + (lane & 7) + ((lane >> 4) << 3));
                uint32_t boff = brow * MM_ROWB + kk * 32 + ((lane >> 3) & 1) * 16;
                ldsm_x4(bh[2*nq][0], bh[2*nq][1], bh[2*nq+1][0], bh[2*nq+1][1], sB_h + boff);
                ldsm_x4(bl[2*nq][0], bl[2*nq][1], bl[2*nq+1][0], bl[2*nq+1][1], sB_l + boff);
            }
            #pragma unroll
            for (int mt = 0; mt < 2; mt++)
                #pragma unroll
                for (int nt = 0; nt < 8; nt++) {
                    mma_bf16(acc[mt][nt], ah[mt], bh[nt]);   // hi*hi
                    mma_bf16(acc[mt][nt], ah[mt], bl[nt]);   // hi*lo
                    mma_bf16(acc[mt][nt], al[mt], bh[nt]);   // lo*hi
                }
        }
        __syncthreads();
        if (c + 2 < NCHUNK) issue(c + 2);
    }

    // epilogue (r6 verbatim): fp32 float2 stores, predicate col < 15000
    #pragma unroll
    for (int mt = 0; mt < 2; mt++) {
        int row = m0 + wm + mt * 16 + (lane >> 2);
        float* r0p = g_t + (size_t)row * TSTRIDE;
        float* r1p = r0p + (size_t)8 * TSTRIDE;
        #pragma unroll
        for (int nt = 0; nt < 8; nt++) {
            int col = n0 + wn + nt * 8 + 2 * (lane & 3);
            if (col < TSTRIDE) {
                *reinterpret_cast<float2*>(r0p + col) = make_float2(acc[mt][nt][0], acc[mt][nt][1]);
                *reinterpret_cast<float2*>(r1p + col) = make_float2(acc[mt][nt][2], acc[mt][nt][3]);
            }
        }
    }
}

// ---------------------------------------------------------------------------
// Stage-2 GEMM, tf32 single-pass (per b):
//   btp[6400 x 128] = T_b[6400 x 300] @ e2_b[128 x 300]^T
// T_b rows r=(i*50+k) are contiguous in g_t with stride 300.
// fp32 loaded via cp.async (zero-filled to K=320), fragments via LDS + cvt.rna.
// ---------------------------------------------------------------------------
#define BT_THREADS 256
#define BT_KC 32
#define BT_ROWB 144                       // 32 fp32 (128B) + 16B pad
#define BT_TILE (128 * BT_ROWB)           // 18432
#define BT_STAGE (2 * BT_TILE)            // A + B = 36864
#define BT_SMEM (2 * BT_STAGE)            // 73728
#define BT_NCH 10

__global__ __launch_bounds__(BT_THREADS, 2)
void btp_tf32_kernel(const float* __restrict__ e2) {
    extern __shared__ char smem[];
    uint32_t sb = smem_u32(smem);
    int tid  = threadIdx.x;
    int lane = tid & 31;
    int w    = tid >> 5;
    int wm   = (w >> 1) * 32;             // 0,32,64,96
    int wn   = (w & 1) * 64;              // 0,64
    int m0 = blockIdx.x * 128;            // in 6400
    int b  = blockIdx.y;

    const float* A = g_t + (size_t)b * 6400 * DDIM + (size_t)m0 * DDIM;
    const float* B = e2 + (size_t)b * 128 * DDIM;

    float acc[2][8][4];
    #pragma unroll
    for (int mt = 0; mt < 2; mt++)
        #pragma unroll
        for (int nt = 0; nt < 8; nt++)
            #pragma unroll
            for (int q = 0; q < 4; q++) acc[mt][nt][q] = 0.f;

    auto issue = [&](int c) {
        int d0 = c * BT_KC;
        uint32_t stage = sb + (c & 1) * BT_STAGE;
        #pragma unroll
        for (int it = 0; it < 8; it++) {
            int i = tid + BT_THREADS * it;        // 0..2047
            bool isA = (i < 1024);
            int idx = i & 1023;
            int r = idx >> 3, c4 = idx & 7;       // 128 rows x 8 float4
            int colb = d0 + c4 * 4;               // first fp32 col of this 16B
            int nb = (colb + 4 <= DDIM) ? 16 : 0; // K tail: zero-fill
            const float* src = (isA ? A : B) + (size_t)r * DDIM + (nb ? colb : 0);
            uint32_t dst = stage + (isA ? 0 : BT_TILE) + r * BT_ROWB + c4 * 16;
            cpasync16z(dst, src, nb);
        }
        asm volatile("cp.async.commit_group;" ::: "memory");
    };

    int g  = lane >> 2;                   // 0..7
    int t4 = lane & 3;                    // 0..3

    issue(0);
    issue(1);

    for (int c = 0; c < BT_NCH; c++) {
        if (c + 1 < BT_NCH) {
            asm volatile("cp.async.wait_group 1;" ::: "memory");
        } else {
            asm volatile("cp.async.wait_group 0;" ::: "memory");
        }
        __syncthreads();

        uint32_t sA = sb + (c & 1) * BT_STAGE;
        uint32_t sB = sA + BT_TILE;
        #pragma unroll
        for (int kk = 0; kk < BT_KC / 8; kk++) {
            uint32_t kbase = (uint32_t)(kk * 8 + t4) * 4;
            // A fragments: m16n8k8 layout
            uint32_t afr[2][4];
            #pragma unroll
            for (int mt = 0; mt < 2; mt++) {
                uint32_t r0 = sA + (uint32_t)(wm + mt * 16 + g) * BT_ROWB + kbase;
                uint32_t r1 = r0 + 8 * BT_ROWB;
                afr[mt][0] = f2tf32(lds_f32(r0));
                afr[mt][1] = f2tf32(lds_f32(r1));
                afr[mt][2] = f2tf32(lds_f32(r0 + 16));
                afr[mt][3] = f2tf32(lds_f32(r1 + 16));
            }
            // B fragments (stored [n][k] rows)
            uint32_t bfr[8][2];
            #pragma unroll
            for (int nt = 0; nt < 8; nt++) {
                uint32_t ba = sB + (uint32_t)(wn + nt * 8 + g) * BT_ROWB + kbase;
                bfr[nt][0] = f2tf32(lds_f32(ba));
                bfr[nt][1] = f2tf32(lds_f32(ba + 16));
            }
            #pragma unroll
            for (int mt = 0; mt < 2; mt++)
                #pragma unroll
                for (int nt = 0; nt < 8; nt++)
                    mma_tf32(acc[mt][nt], afr[mt], bfr[nt]);
        }
        __syncthreads();
        if (c + 2 < BT_NCH) issue(c + 2);
    }

    // epilogue: fp32 btp -> g_btp[b][m0+row][col]
    float* dst = g_btp + (size_t)b * 6400 * 128;
    #pragma unroll
    for (int mt = 0; mt < 2; mt++) {
        int row = m0 + wm + mt * 16 + (lane >> 2);
        float* r0p = dst + (size_t)row * 128 + wn;
        float* r1p = r0p + 8 * 128;
        #pragma unroll
        for (int nt = 0; nt < 8; nt++) {
            int coff = nt * 8 + 2 * (lane & 3);
            *reinterpret_cast<float2*>(r0p + coff) = make_float2(acc[mt][nt][0], acc[mt][nt][1]);
            *reinterpret_cast<float2*>(r1p + coff) = make_float2(acc[mt][nt][2], acc[mt][nt][3]);
        }
    }
}

// ---------------------------------------------------------------------------
// gate epilogue: out[b,i,j] = sum_k u_k*( g*btp + (1-g)*tanh(sd) + bb_k )
// ---------------------------------------------------------------------------
#define G_P2LD 129
#define G_SMEM ((2 * KDIM * G_P2LD + 5 * 64) * 4)

__global__ __launch_bounds__(128)
void gate_kernel(const float* __restrict__ bg,
                 const float* __restrict__ bb,
                 const float* __restrict__ u,
                 float* __restrict__ out) {
    extern __shared__ float sm[];
    float* p2dS = sm;
    float* p2gS = sm + KDIM * G_P2LD;
    float* p1dS = p2gS + KDIM * G_P2LD;
    float* p1gS = p1dS + 64;
    float* uS   = p1gS + 64;
    float* bgS  = uS + 64;
    float* bbS  = bgS + 64;

    int blk = blockIdx.x;                 // b*128 + i
    int b   = blk >> 7;
    int tid = threadIdx.x;                // j

    const float* p2d_b = g_p2d + (size_t)b * 128 * KDIM;
    const float* p2g_b = g_p2g + (size_t)b * 128 * KDIM;
    for (int idx = tid; idx < 128 * KDIM; idx += 128) {
        int j = idx / KDIM, k = idx - j * KDIM;
        p2dS[k * G_P2LD + j] = p2d_b[idx];
        p2gS[k * G_P2LD + j] = p2g_b[idx];
    }
    if (tid < KDIM) {
        p1dS[tid] = g_p1d[(size_t)blk * KDIM + tid];
        p1gS[tid] = g_p1g[(size_t)blk * KDIM + tid];
        uS[tid]   = u[tid];
        bgS[tid]  = bg[tid];
        bbS[tid]  = bb[tid];
    }
    __syncthreads();

    const float* btp_row = g_btp + (size_t)b * 6400 * 128 + (size_t)(blk & 127) * KDIM * 128;

    float acc = 0.f;
    #pragma unroll 5
    for (int k = 0; k < KDIM; k++) {
        float btp = btp_row[k * 128 + tid];
        float sd  = p1dS[k] + p2dS[k * G_P2LD + tid];
        float sg  = p1gS[k] + p2gS[k * G_P2LD + tid] + bgS[k];
        float e   = __expf(-sg);
        float g   = __fdividef(1.f, 1.f + e);
        float sln = tanh_hw(sd);
        float mix = fmaf(g, btp - sln, sln) + bbS[k];
        acc = fmaf(uS[k], mix, acc);
    }
    out[(size_t)blk * 128 + tid] = acc;
}

// ---------------------------------------------------------------------------
// projections: warp = one 4-row group, lanes = consecutive k.
// ---------------------------------------------------------------------------
#define P_ROWS 32
#define P_THREADS 512
#define P_SMEM ((DDIM * KDIM + DDIM * P_ROWS) * 4)

__global__ __launch_bounds__(P_THREADS)
void proj_kernel(const float* __restrict__ e1,
                 const float* __restrict__ e2,
                 const float* __restrict__ Wd,
                 const float* __restrict__ Wg) {
    extern __shared__ float sm[];
    float* WS   = sm;                    // [300][50]
    float* rowS = sm + DDIM * KDIM;      // [300][32]

    int blk = blockIdx.x;
    int rt  = blk & 127;
    int mt  = (blk >> 7) & 1;
    int s   = blk >> 8;
    int row0 = rt * P_ROWS;
    int tid = threadIdx.x;

    const float* E = s ? e2 : e1;
    const float* W = (mt ? Wg : Wd) + s * DDIM * KDIM;
    float* out = s ? (mt ? g_p2g : g_p2d) : (mt ? g_p1g : g_p1d);

    const float4* W4 = reinterpret_cast<const float4*>(W);
    float4* WS4 = reinterpret_cast<float4*>(WS);
    for (int i = tid; i < DDIM * KDIM / 4; i += P_THREADS) WS4[i] = W4[i];

    for (int i = tid; i < P_ROWS * (DDIM / 4); i += P_THREADS) {
        int r = i / (DDIM / 4);
        int c4 = i % (DDIM / 4);
        float4 v = *reinterpret_cast<const float4*>(&E[(size_t)(row0 + r) * DDIM + 4 * c4]);
        rowS[(4 * c4 + 0) * P_ROWS + r] = v.x;
        rowS[(4 * c4 + 1) * P_ROWS + r] = v.y;
        rowS[(4 * c4 + 2) * P_ROWS + r] = v.z;
        rowS[(4 * c4 + 3) * P_ROWS + r] = v.w;
    }
    __syncthreads();

    int k  = tid & 63;
    int r4 = tid >> 6;                   // 0..7
    if (k < KDIM) {
        float4 acc = make_float4(0.f, 0.f, 0.f, 0.f);
        #pragma unroll 4
        for (int d = 0; d < DDIM; d++) {
            float4 x = *reinterpret_cast<const float4*>(&rowS[d * P_ROWS + r4 * 4]);
            float w = WS[d * KDIM + k];
            acc.x = fmaf(x.x, w, acc.x);
            acc.y = fmaf(x.y, w, acc.y);
            acc.z = fmaf(x.z, w, acc.z);
            acc.w = fmaf(x.w, w, acc.w);
        }
        int rb = row0 + r4 * 4;
        out[(size_t)(rb + 0) * KDIM + k] = acc.x;
        out[(size_t)(rb + 1) * KDIM + k] = acc.y;
        out[(size_t)(rb + 2) * KDIM + k] = acc.z;
        out[(size_t)(rb + 3) * KDIM + k] = acc.w;
    }
}

// ---------------------------------------------------------------------------
extern "C" void kernel_launch(void* const* d_in, const int* in_sizes, int n_in,
                              void* d_out, int out_size) {
    const float* e1 = (const float*)d_in[0];
    const float* e2 = (const float*)d_in[1];
    const float* Wb = (const float*)d_in[2];
    const float* Wd = (const float*)d_in[3];
    const float* Wg = (const float*)d_in[4];
    const float* bg = (const float*)d_in[5];
    const float* bb = (const float*)d_in[6];
    const float* u  = (const float*)d_in[7];
    float* out = (float*)d_out;

    cudaFuncSetAttribute(proj_kernel, cudaFuncAttributeMaxDynamicSharedMemorySize, P_SMEM);
    cudaFuncSetAttribute(tmat_mma_kernel, cudaFuncAttributeMaxDynamicSharedMemorySize, MM_SMEM);
    cudaFuncSetAttribute(btp_tf32_kernel, cudaFuncAttributeMaxDynamicSharedMemorySize, BT_SMEM);
    cudaFuncSetAttribute(gate_kernel, cudaFuncAttributeMaxDynamicSharedMemorySize, G_SMEM);

    convA_kernel<<<ROWS1, KPAD>>>(e1);
    convB_kernel<<<dim3(10, 10, KDIM), dim3(32, 8)>>>(Wb);
    proj_kernel<<<512, P_THREADS, P_SMEM>>>(e1, e2, Wd, Wg);
    tmat_mma_kernel<<<dim3(ROWS1 / 128, NPAD / 128), MM_THREADS, MM_SMEM>>>();
    btp_tf32_kernel<<<dim3(6400 / 128, BDIM), BT_THREADS, BT_SMEM>>>(e2);
    gate_kernel<<<ROWS1, 128, G_SMEM>>>(bg, bb, u, out);
}

// round 12
// speedup vs baseline: 1.3470x; 1.1207x over previous
#include <cuda_runtime.h>
#include <cuda_bf16.h>
#include <math.h>
#include <stdint.h>

#define BDIM 32
#define L1DIM 128
#define L2DIM 128
#define DDIM 300
#define KDIM 50
#define ROWS1 (BDIM * L1DIM)   // 4096
#define ROWS2 (BDIM * L2DIM)   // 4096
#define NPAD 15104             // 118*128 compact (k*300+e) rows for Wb'
#define TSTRIDE (KDIM * DDIM)  // 15000

// Scratch (__device__ globals; zero-initialized at module load; pad regions
// never written so they stay zero across graph replays)
__device__ float g_t[(size_t)ROWS1 * TSTRIDE];           // 245.8 MB fp32 t
__device__ float g_btp[(size_t)BDIM * 6400 * 128];       // 104.9 MB
__device__ float g_wbt[(size_t)NPAD * DDIM];             // 18.1 MB Wb'[(k*300+e)][d]
__device__ float g_p1d[ROWS1 * KDIM];
__device__ float g_p1g[ROWS1 * KDIM];
__device__ float g_p2d[ROWS2 * KDIM];
__device__ float g_p2g[ROWS2 * KDIM];

// ---------------------------------------------------------------------------
// helpers (plain sm_80+ PTX)
// ---------------------------------------------------------------------------
__device__ __forceinline__ uint32_t smem_u32(const void* p) {
    uint32_t a;
    asm("{ .reg .u64 t; cvta.to.shared.u64 t, %1; cvt.u32.u64 %0, t; }" : "=r"(a) : "l"(p));
    return a;
}
__device__ __forceinline__ void cpasync16z(uint32_t dst, const void* src, int nb) {
    asm volatile("cp.async.cg.shared.global [%0], [%1], 16, %2;"
                 :: "r"(dst), "l"(src), "r"(nb));
}
__device__ __forceinline__ void mma_tf32(float* c, const uint32_t* a, const uint32_t* b) {
    asm volatile(
        "mma.sync.aligned.m16n8k8.row.col.f32.tf32.tf32.f32 "
        "{%0,%1,%2,%3}, {%4,%5,%6,%7}, {%8,%9}, {%0,%1,%2,%3};"
        : "+f"(c[0]), "+f"(c[1]), "+f"(c[2]), "+f"(c[3])
        : "r"(a[0]), "r"(a[1]), "r"(a[2]), "r"(a[3]), "r"(b[0]), "r"(b[1]));
}
__device__ __forceinline__ float lds_f32(uint32_t a) {
    float v;
    asm volatile("ld.shared.f32 %0, [%1];" : "=f"(v) : "r"(a));
    return v;
}
__device__ __forceinline__ uint32_t f2tf32(float f) {
    uint32_t r;
    asm("cvt.rna.tf32.f32 %0, %1;" : "=r"(r) : "f"(f));
    return r;
}
__device__ __forceinline__ float tanh_hw(float x) {
    float y;
    asm("tanh.approx.f32 %0, %1;" : "=f"(y) : "f"(x));
    return y;
}

// ---------------------------------------------------------------------------
// convB: Wb[k][d][e] -> Wb'[(k*300+e)][d] fp32 (compact, transposed per k)
// ---------------------------------------------------------------------------
__global__ void convB_kernel(const float* __restrict__ Wb) {
    __shared__ float tile[32][33];
    int k  = blockIdx.z;
    int d0 = blockIdx.x * 32;
    int e0 = blockIdx.y * 32;
    int tx = threadIdx.x, ty = threadIdx.y;   // 32 x 8
    #pragma unroll
    for (int q = 0; q < 4; q++) {
        int d = d0 + ty + 8 * q;
        int e = e0 + tx;
        float v = 0.f;
        if (d < DDIM && e < DDIM)
            v = Wb[(size_t)k * DDIM * DDIM + (size_t)d * DDIM + e];
        tile[ty + 8 * q][tx] = v;
    }
    __syncthreads();
    #pragma unroll
    for (int q = 0; q < 4; q++) {
        int e = e0 + ty + 8 * q;
        int d = d0 + tx;
        if (e < DDIM && d < DDIM)
            g_wbt[(size_t)(k * DDIM + e) * DDIM + d] = tile[tx][ty + 8 * q];
    }
}

// ---------------------------------------------------------------------------
// tf32 GEMM core: CTA 128x128, 8 warps 4(m)x2(n) -> warp 32x64, KC=32,
// 2-stage cp.async, fp32 smem tiles (stride DDIM inputs, K-tail zero-fill),
// fragments via conflict-free LDS + cvt.rna.tf32. 72 KB smem, 2 CTAs/SM.
// ---------------------------------------------------------------------------
#define BT_THREADS 256
#define BT_KC 32
#define BT_ROWB 144                       // 32 fp32 (128B) + 16B pad
#define BT_TILE (128 * BT_ROWB)           // 18432
#define BT_STAGE (2 * BT_TILE)            // A + B = 36864
#define BT_SMEM (2 * BT_STAGE)            // 73728
#define BT_NCH 10                         // ceil(300/32) = 10 (tail zero-filled)

struct Tf32Core {
    uint32_t sb;
    int tid, lane, wm, wn;
    const float *A, *B;
    float acc[2][8][4];

    __device__ __forceinline__ void init(uint32_t sb_, int tid_,
                                         const float* A_, const float* B_) {
        sb = sb_; tid = tid_;
        lane = tid & 31;
        int w = tid >> 5;
        wm = (w >> 1) * 32;               // 0,32,64,96
        wn = (w & 1) * 64;                // 0,64
        A = A_; B = B_;
        #pragma unroll
        for (int mt = 0; mt < 2; mt++)
            #pragma unroll
            for (int nt = 0; nt < 8; nt++)
                #pragma unroll
                for (int q = 0; q < 4; q++) acc[mt][nt][q] = 0.f;
    }

    __device__ __forceinline__ void issue(int c) {
        int d0 = c * BT_KC;
        uint32_t stage = sb + (c & 1) * BT_STAGE;
        #pragma unroll
        for (int it = 0; it < 8; it++) {
            int i = tid + BT_THREADS * it;        // 0..2047
            bool isA = (i < 1024);
            int idx = i & 1023;
            int r = idx >> 3, c4 = idx & 7;       // 128 rows x 8 float4
            int colb = d0 + c4 * 4;
            int nb = (colb + 4 <= DDIM) ? 16 : 0; // K tail: zero-fill
            const float* src = (isA ? A : B) + (size_t)r * DDIM + (nb ? colb : 0);
            uint32_t dst = stage + (isA ? 0 : BT_TILE) + r * BT_ROWB + c4 * 16;
            cpasync16z(dst, src, nb);
        }
        asm volatile("cp.async.commit_group;" ::: "memory");
    }

    __device__ __forceinline__ void compute(int c) {
        int g  = lane >> 2;               // 0..7
        int t4 = lane & 3;                // 0..3
        uint32_t sA = sb + (c & 1) * BT_STAGE;
        uint32_t sB = sA + BT_TILE;
        #pragma unroll
        for (int kk = 0; kk < BT_KC / 8; kk++) {
            uint32_t kbase = (uint32_t)(kk * 8 + t4) * 4;
            uint32_t afr[2][4];
            #pragma unroll
            for (int mt = 0; mt < 2; mt++) {
                uint32_t r0 = sA + (uint32_t)(wm + mt * 16 + g) * BT_ROWB + kbase;
                uint32_t r1 = r0 + 8 * BT_ROWB;
                afr[mt][0] = f2tf32(lds_f32(r0));
                afr[mt][1] = f2tf32(lds_f32(r1));
                afr[mt][2] = f2tf32(lds_f32(r0 + 16));
                afr[mt][3] = f2tf32(lds_f32(r1 + 16));
            }
            uint32_t bfr[8][2];
            #pragma unroll
            for (int nt = 0; nt < 8; nt++) {
                uint32_t ba = sB + (uint32_t)(wn + nt * 8 + g) * BT_ROWB + kbase;
                bfr[nt][0] = f2tf32(lds_f32(ba));
                bfr[nt][1] = f2tf32(lds_f32(ba + 16));
            }
            #pragma unroll
            for (int mt = 0; mt < 2; mt++)
                #pragma unroll
                for (int nt = 0; nt < 8; nt++)
                    mma_tf32(acc[mt][nt], afr[mt], bfr[nt]);
        }
    }

    __device__ __forceinline__ void run() {
        issue(0);
        issue(1);
        for (int c = 0; c < BT_NCH; c++) {
            if (c + 1 < BT_NCH) {
                asm volatile("cp.async.wait_group 1;" ::: "memory");
            } else {
                asm volatile("cp.async.wait_group 0;" ::: "memory");
            }
            __syncthreads();
            compute(c);
            __syncthreads();
            if (c + 2 < BT_NCH) issue(c + 2);
        }
    }
};

// ---------------------------------------------------------------------------
// Stage-1 (tf32): t[4096 x 15000] = e1[4096 x 300] @ Wb'[15104 x 300]^T
// ---------------------------------------------------------------------------
__global__ __launch_bounds__(BT_THREADS, 2)
void tmat_tf32_kernel(const float* __restrict__ e1) {
    extern __shared__ char smem[];
    Tf32Core g;
    int m0 = blockIdx.x * 128;            // in 4096
    int n0 = blockIdx.y * 128;            // in 15104
    g.init(smem_u32(smem), threadIdx.x,
           e1 + (size_t)m0 * DDIM,
           g_wbt + (size_t)n0 * DDIM);
    g.run();

    #pragma unroll
    for (int mt = 0; mt < 2; mt++) {
        int row = m0 + g.wm + mt * 16 + (g.lane >> 2);
        float* r0p = g_t + (size_t)row * TSTRIDE;
        float* r1p = r0p + (size_t)8 * TSTRIDE;
        #pragma unroll
        for (int nt = 0; nt < 8; nt++) {
            int col = n0 + g.wn + nt * 8 + 2 * (g.lane & 3);
            if (col < TSTRIDE) {
                *reinterpret_cast<float2*>(r0p + col) = make_float2(g.acc[mt][nt][0], g.acc[mt][nt][1]);
                *reinterpret_cast<float2*>(r1p + col) = make_float2(g.acc[mt][nt][2], g.acc[mt][nt][3]);
            }
        }
    }
}

// ---------------------------------------------------------------------------
// Stage-2 (tf32, per b): btp[6400 x 128] = T_b[6400 x 300] @ e2_b[128 x 300]^T
// ---------------------------------------------------------------------------
__global__ __launch_bounds__(BT_THREADS, 2)
void btp_tf32_kernel(const float* __restrict__ e2) {
    extern __shared__ char smem[];
    Tf32Core g;
    int m0 = blockIdx.x * 128;            // in 6400
    int b  = blockIdx.y;
    g.init(smem_u32(smem), threadIdx.x,
           g_t + (size_t)b * 6400 * DDIM + (size_t)m0 * DDIM,
           e2 + (size_t)b * 128 * DDIM);
    g.run();

    float* dst = g_btp + (size_t)b * 6400 * 128;
    #pragma unroll
    for (int mt = 0; mt < 2; mt++) {
        int row = m0 + g.wm + mt * 16 + (g.lane >> 2);
        float* r0p = dst + (size_t)row * 128 + g.wn;
        float* r1p = r0p + 8 * 128;
        #pragma unroll
        for (int nt = 0; nt < 8; nt++) {
            int coff = nt * 8 + 2 * (g.lane & 3);
            *reinterpret_cast<float2*>(r0p + coff) = make_float2(g.acc[mt][nt][0], g.acc[mt][nt][1]);
            *reinterpret_cast<float2*>(r1p + coff) = make_float2(g.acc[mt][nt][2], g.acc[mt][nt][3]);
        }
    }
}

// ---------------------------------------------------------------------------
// gate epilogue: out[b,i,j] = sum_k u_k*( g*btp + (1-g)*tanh(sd) + bb_k )
// ---------------------------------------------------------------------------
#define G_P2LD 129
#define G_SMEM ((2 * KDIM * G_P2LD + 5 * 64) * 4)

__global__ __launch_bounds__(128)
void gate_kernel(const float* __restrict__ bg,
                 const float* __restrict__ bb,
                 const float* __restrict__ u,
                 float* __restrict__ out) {
    extern __shared__ float sm[];
    float* p2dS = sm;
    float* p2gS = sm + KDIM * G_P2LD;
    float* p1dS = p2gS + KDIM * G_P2LD;
    float* p1gS = p1dS + 64;
    float* uS   = p1gS + 64;
    float* bgS  = uS + 64;
    float* bbS  = bgS + 64;

    int blk = blockIdx.x;                 // b*128 + i
    int b   = blk >> 7;
    int tid = threadIdx.x;                // j

    const float* p2d_b = g_p2d + (size_t)b * 128 * KDIM;
    const float* p2g_b = g_p2g + (size_t)b * 128 * KDIM;
    for (int idx = tid; idx < 128 * KDIM; idx += 128) {
        int j = idx / KDIM, k = idx - j * KDIM;
        p2dS[k * G_P2LD + j] = p2d_b[idx];
        p2gS[k * G_P2LD + j] = p2g_b[idx];
    }
    if (tid < KDIM) {
        p1dS[tid] = g_p1d[(size_t)blk * KDIM + tid];
        p1gS[tid] = g_p1g[(size_t)blk * KDIM + tid];
        uS[tid]   = u[tid];
        bgS[tid]  = bg[tid];
        bbS[tid]  = bb[tid];
    }
    __syncthreads();

    const float* btp_row = g_btp + (size_t)b * 6400 * 128 + (size_t)(blk & 127) * KDIM * 128;

    float acc = 0.f;
    #pragma unroll 5
    for (int k = 0; k < KDIM; k++) {
        float btp = btp_row[k * 128 + tid];
        float sd  = p1dS[k] + p2dS[k * G_P2LD + tid];
        float sg  = p1gS[k] + p2gS[k * G_P2LD + tid] + bgS[k];
        float e   = __expf(-sg);
        float g   = __fdividef(1.f, 1.f + e);
        float sln = tanh_hw(sd);
        float mix = fmaf(g, btp - sln, sln) + bbS[k];
        acc = fmaf(uS[k], mix, acc);
    }
    out[(size_t)blk * 128 + tid] = acc;
}

// ---------------------------------------------------------------------------
// projections: warp = one 4-row group, lanes = consecutive k.
// ---------------------------------------------------------------------------
#define P_ROWS 32
#define P_THREADS 512
#define P_SMEM ((DDIM * KDIM + DDIM * P_ROWS) * 4)

__global__ __launch_bounds__(P_THREADS)
void proj_kernel(const float* __restrict__ e1,
                 const float* __restrict__ e2,
                 const float* __restrict__ Wd,
                 const float* __restrict__ Wg) {
    extern __shared__ float sm[];
    float* WS   = sm;                    // [300][50]
    float* rowS = sm + DDIM * KDIM;      // [300][32]

    int blk = blockIdx.x;
    int rt  = blk & 127;
    int mt  = (blk >> 7) & 1;
    int s   = blk >> 8;
    int row0 = rt * P_ROWS;
    int tid = threadIdx.x;

    const float* E = s ? e2 : e1;
    const float* W = (mt ? Wg : Wd) + s * DDIM * KDIM;
    float* out = s ? (mt ? g_p2g : g_p2d) : (mt ? g_p1g : g_p1d);

    const float4* W4 = reinterpret_cast<const float4*>(W);
    float4* WS4 = reinterpret_cast<float4*>(WS);
    for (int i = tid; i < DDIM * KDIM / 4; i += P_THREADS) WS4[i] = W4[i];

    for (int i = tid; i < P_ROWS * (DDIM / 4); i += P_THREADS) {
        int r = i / (DDIM / 4);
        int c4 = i % (DDIM / 4);
        float4 v = *reinterpret_cast<const float4*>(&E[(size_t)(row0 + r) * DDIM + 4 * c4]);
        rowS[(4 * c4 + 0) * P_ROWS + r] = v.x;
        rowS[(4 * c4 + 1) * P_ROWS + r] = v.y;
        rowS[(4 * c4 + 2) * P_ROWS + r] = v.z;
        rowS[(4 * c4 + 3) * P_ROWS + r] = v.w;
    }
    __syncthreads();

    int k  = tid & 63;
    int r4 = tid >> 6;                   // 0..7
    if (k < KDIM) {
        float4 acc = make_float4(0.f, 0.f, 0.f, 0.f);
        #pragma unroll 4
        for (int d = 0; d < DDIM; d++) {
            float4 x = *reinterpret_cast<const float4*>(&rowS[d * P_ROWS + r4 * 4]);
            float w = WS[d * KDIM + k];
            acc.x = fmaf(x.x, w, acc.x);
            acc.y = fmaf(x.y, w, acc.y);
            acc.z = fmaf(x.z, w, acc.z);
            acc.w = fmaf(x.w, w, acc.w);
        }
        int rb = row0 + r4 * 4;
        out[(size_t)(rb + 0) * KDIM + k] = acc.x;
        out[(size_t)(rb + 1) * KDIM + k] = acc.y;
        out[(size_t)(rb + 2) * KDIM + k] = acc.z;
        out[(size_t)(rb + 3) * KDIM + k] = acc.w;
    }
}

// ---------------------------------------------------------------------------
extern "C" void kernel_launch(void* const* d_in, const int* in_sizes, int n_in,
                              void* d_out, int out_size) {
    const float* e1 = (const float*)d_in[0];
    const float* e2 = (const float*)d_in[1];
    const float* Wb = (const float*)d_in[2];
    const float* Wd = (const float*)d_in[3];
    const float* Wg = (const float*)d_in[4];
    const float* bg = (const float*)d_in[5];
    const float* bb = (const float*)d_in[6];
    const float* u  = (const float*)d_in[7];
    float* out = (float*)d_out;

    cudaFuncSetAttribute(proj_kernel, cudaFuncAttributeMaxDynamicSharedMemorySize, P_SMEM);
    cudaFuncSetAttribute(tmat_tf32_kernel, cudaFuncAttributeMaxDynamicSharedMemorySize, BT_SMEM);
    cudaFuncSetAttribute(btp_tf32_kernel, cudaFuncAttributeMaxDynamicSharedMemorySize, BT_SMEM);
    cudaFuncSetAttribute(gate_kernel, cudaFuncAttributeMaxDynamicSharedMemorySize, G_SMEM);

    convB_kernel<<<dim3(10, 10, KDIM), dim3(32, 8)>>>(Wb);
    proj_kernel<<<512, P_THREADS, P_SMEM>>>(e1, e2, Wd, Wg);
    tmat_tf32_kernel<<<dim3(ROWS1 / 128, NPAD / 128), BT_THREADS, BT_SMEM>>>(e1);
    btp_tf32_kernel<<<dim3(6400 / 128, BDIM), BT_THREADS, BT_SMEM>>>(e2);
    gate_kernel<<<ROWS1, 128, G_SMEM>>>(bg, bb, u, out);
}

// round 13
// speedup vs baseline: 1.3924x; 1.0337x over previous
#include <cuda_runtime.h>
#include <cuda_bf16.h>
#include <math.h>
#include <stdint.h>

#define BDIM 32
#define L1DIM 128
#define L2DIM 128
#define DDIM 300
#define KDIM 50
#define ROWS1 (BDIM * L1DIM)   // 4096
#define ROWS2 (BDIM * L2DIM)   // 4096
#define NPAD 15104             // 118*128 compact (k*300+e) rows for Wb'
#define TSTRIDE (KDIM * DDIM)  // 15000

// Scratch (__device__ globals; zero-initialized at module load; pad regions
// never written so they stay zero across graph replays)
__device__ float g_t[(size_t)ROWS1 * TSTRIDE];           // 245.8 MB tf32-rounded t
__device__ float g_btp[(size_t)BDIM * 6400 * 128];       // 104.9 MB
__device__ float g_wbt[(size_t)NPAD * DDIM];             // 18.1 MB tf32 Wb'[(k*300+e)][d]
__device__ float g_e1t[(size_t)ROWS1 * DDIM];            // 4.9 MB tf32 e1
__device__ float g_e2t[(size_t)ROWS2 * DDIM];            // 4.9 MB tf32 e2
__device__ float g_p1d[ROWS1 * KDIM];
__device__ float g_p1g[ROWS1 * KDIM];
__device__ float g_p2d[ROWS2 * KDIM];
__device__ float g_p2g[ROWS2 * KDIM];

// ---------------------------------------------------------------------------
// helpers (plain sm_80+ PTX)
// ---------------------------------------------------------------------------
__device__ __forceinline__ uint32_t smem_u32(const void* p) {
    uint32_t a;
    asm("{ .reg .u64 t; cvta.to.shared.u64 t, %1; cvt.u32.u64 %0, t; }" : "=r"(a) : "l"(p));
    return a;
}
__device__ __forceinline__ void cpasync16z(uint32_t dst, const void* src, int nb) {
    asm volatile("cp.async.cg.shared.global [%0], [%1], 16, %2;"
                 :: "r"(dst), "l"(src), "r"(nb));
}
__device__ __forceinline__ void mma_tf32(float* c, const uint32_t* a, const uint32_t* b) {
    asm volatile(
        "mma.sync.aligned.m16n8k8.row.col.f32.tf32.tf32.f32 "
        "{%0,%1,%2,%3}, {%4,%5,%6,%7}, {%8,%9}, {%0,%1,%2,%3};"
        : "+f"(c[0]), "+f"(c[1]), "+f"(c[2]), "+f"(c[3])
        : "r"(a[0]), "r"(a[1]), "r"(a[2]), "r"(a[3]), "r"(b[0]), "r"(b[1]));
}
__device__ __forceinline__ uint32_t lds_u32(uint32_t a) {
    uint32_t v;
    asm volatile("ld.shared.b32 %0, [%1];" : "=r"(v) : "r"(a));
    return v;
}
__device__ __forceinline__ uint32_t f2tf32(float f) {
    uint32_t r;
    asm("cvt.rna.tf32.f32 %0, %1;" : "=r"(r) : "f"(f));
    return r;
}
__device__ __forceinline__ float tf32r(float f) {
    return __uint_as_float(f2tf32(f));
}
__device__ __forceinline__ float tanh_hw(float x) {
    float y;
    asm("tanh.approx.f32 %0, %1;" : "=f"(y) : "f"(x));
    return y;
}

// ---------------------------------------------------------------------------
// convE: e1/e2 fp32 -> tf32-rounded fp32 copies
// ---------------------------------------------------------------------------
__global__ void convE_kernel(const float* __restrict__ e1,
                             const float* __restrict__ e2) {
    int m = blockIdx.x;                  // 0..8191
    int d = threadIdx.x;                 // 0..319
    if (d >= DDIM) return;
    bool s2 = (m >= ROWS1);
    int row = s2 ? m - ROWS1 : m;
    const float* src = s2 ? e2 : e1;
    float* dst = s2 ? g_e2t : g_e1t;
    dst[(size_t)row * DDIM + d] = tf32r(src[(size_t)row * DDIM + d]);
}

// ---------------------------------------------------------------------------
// convB: Wb[k][d][e] -> tf32-rounded Wb'[(k*300+e)][d]
// ---------------------------------------------------------------------------
__global__ void convB_kernel(const float* __restrict__ Wb) {
    __shared__ float tile[32][33];
    int k  = blockIdx.z;
    int d0 = blockIdx.x * 32;
    int e0 = blockIdx.y * 32;
    int tx = threadIdx.x, ty = threadIdx.y;   // 32 x 8
    #pragma unroll
    for (int q = 0; q < 4; q++) {
        int d = d0 + ty + 8 * q;
        int e = e0 + tx;
        float v = 0.f;
        if (d < DDIM && e < DDIM)
            v = Wb[(size_t)k * DDIM * DDIM + (size_t)d * DDIM + e];
        tile[ty + 8 * q][tx] = v;
    }
    __syncthreads();
    #pragma unroll
    for (int q = 0; q < 4; q++) {
        int e = e0 + ty + 8 * q;
        int d = d0 + tx;
        if (e < DDIM && d < DDIM)
            g_wbt[(size_t)(k * DDIM + e) * DDIM + d] = tf32r(tile[tx][ty + 8 * q]);
    }
}

// ---------------------------------------------------------------------------
// tf32 GEMM core: CTA 128x128, 8 warps 4(m)x2(n) -> warp 32x64, KC=32,
// 2-stage cp.async, fp32 smem tiles (stride DDIM inputs, K-tail zero-fill),
// fragments via conflict-free LDS (operands pre-rounded to tf32 in memory).
// 72 KB smem, 2 CTAs/SM.
// ---------------------------------------------------------------------------
#define BT_THREADS 256
#define BT_KC 32
#define BT_ROWB 144                       // 32 fp32 (128B) + 16B pad
#define BT_TILE (128 * BT_ROWB)           // 18432
#define BT_STAGE (2 * BT_TILE)            // A + B = 36864
#define BT_SMEM (2 * BT_STAGE)            // 73728
#define BT_NCH 10                         // ceil(300/32) (tail zero-filled)

struct Tf32Core {
    uint32_t sb;
    int tid, lane, wm, wn;
    const float *A, *B;
    float acc[2][8][4];

    __device__ __forceinline__ void init(uint32_t sb_, int tid_,
                                         const float* A_, const float* B_) {
        sb = sb_; tid = tid_;
        lane = tid & 31;
        int w = tid >> 5;
        wm = (w >> 1) * 32;               // 0,32,64,96
        wn = (w & 1) * 64;                // 0,64
        A = A_; B = B_;
        #pragma unroll
        for (int mt = 0; mt < 2; mt++)
            #pragma unroll
            for (int nt = 0; nt < 8; nt++)
                #pragma unroll
                for (int q = 0; q < 4; q++) acc[mt][nt][q] = 0.f;
    }

    __device__ __forceinline__ void issue(int c) {
        int d0 = c * BT_KC;
        uint32_t stage = sb + (c & 1) * BT_STAGE;
        #pragma unroll
        for (int it = 0; it < 8; it++) {
            int i = tid + BT_THREADS * it;        // 0..2047
            bool isA = (i < 1024);
            int idx = i & 1023;
            int r = idx >> 3, c4 = idx & 7;       // 128 rows x 8 float4
            int colb = d0 + c4 * 4;
            int nb = (colb + 4 <= DDIM) ? 16 : 0; // K tail: zero-fill
            const float* src = (isA ? A : B) + (size_t)r * DDIM + (nb ? colb : 0);
            uint32_t dst = stage + (isA ? 0 : BT_TILE) + r * BT_ROWB + c4 * 16;
            cpasync16z(dst, src, nb);
        }
        asm volatile("cp.async.commit_group;" ::: "memory");
    }

    __device__ __forceinline__ void compute(int c) {
        int g  = lane >> 2;               // 0..7
        int t4 = lane & 3;                // 0..3
        uint32_t sA = sb + (c & 1) * BT_STAGE;
        uint32_t sB = sA + BT_TILE;
        #pragma unroll
        for (int kk = 0; kk < BT_KC / 8; kk++) {
            uint32_t kbase = (uint32_t)(kk * 8 + t4) * 4;
            uint32_t afr[2][4];
            #pragma unroll
            for (int mt = 0; mt < 2; mt++) {
                uint32_t r0 = sA + (uint32_t)(wm + mt * 16 + g) * BT_ROWB + kbase;
                uint32_t r1 = r0 + 8 * BT_ROWB;
                afr[mt][0] = lds_u32(r0);
                afr[mt][1] = lds_u32(r1);
                afr[mt][2] = lds_u32(r0 + 16);
                afr[mt][3] = lds_u32(r1 + 16);
            }
            uint32_t bfr[8][2];
            #pragma unroll
            for (int nt = 0; nt < 8; nt++) {
                uint32_t ba = sB + (uint32_t)(wn + nt * 8 + g) * BT_ROWB + kbase;
                bfr[nt][0] = lds_u32(ba);
                bfr[nt][1] = lds_u32(ba + 16);
            }
            #pragma unroll
            for (int mt = 0; mt < 2; mt++)
                #pragma unroll
                for (int nt = 0; nt < 8; nt++)
                    mma_tf32(acc[mt][nt], afr[mt], bfr[nt]);
        }
    }

    __device__ __forceinline__ void run() {
        issue(0);
        issue(1);
        for (int c = 0; c < BT_NCH; c++) {
            if (c + 1 < BT_NCH) {
                asm volatile("cp.async.wait_group 1;" ::: "memory");
            } else {
                asm volatile("cp.async.wait_group 0;" ::: "memory");
            }
            __syncthreads();
            compute(c);
            __syncthreads();
            if (c + 2 < BT_NCH) issue(c + 2);
        }
    }
};

// ---------------------------------------------------------------------------
// Stage-1 (tf32): t[4096 x 15000] = e1t[4096 x 300] @ Wb'[15104 x 300]^T
// epilogue stores tf32-rounded values (identical to btp's cvt — no extra error)
// ---------------------------------------------------------------------------
__global__ __launch_bounds__(BT_THREADS, 2)
void tmat_tf32_kernel() {
    extern __shared__ char smem[];
    Tf32Core g;
    int m0 = blockIdx.x * 128;            // in 4096
    int n0 = blockIdx.y * 128;            // in 15104
    g.init(smem_u32(smem), threadIdx.x,
           g_e1t + (size_t)m0 * DDIM,
           g_wbt + (size_t)n0 * DDIM);
    g.run();

    #pragma unroll
    for (int mt = 0; mt < 2; mt++) {
        int row = m0 + g.wm + mt * 16 + (g.lane >> 2);
        float* r0p = g_t + (size_t)row * TSTRIDE;
        float* r1p = r0p + (size_t)8 * TSTRIDE;
        #pragma unroll
        for (int nt = 0; nt < 8; nt++) {
            int col = n0 + g.wn + nt * 8 + 2 * (g.lane & 3);
            if (col < TSTRIDE) {
                *reinterpret_cast<float2*>(r0p + col) =
                    make_float2(tf32r(g.acc[mt][nt][0]), tf32r(g.acc[mt][nt][1]));
                *reinterpret_cast<float2*>(r1p + col) =
                    make_float2(tf32r(g.acc[mt][nt][2]), tf32r(g.acc[mt][nt][3]));
            }
        }
    }
}

// ---------------------------------------------------------------------------
// Stage-2 (tf32, per b): btp[6400 x 128] = T_b[6400 x 300] @ e2t_b[128 x 300]^T
// ---------------------------------------------------------------------------
__global__ __launch_bounds__(BT_THREADS, 2)
void btp_tf32_kernel() {
    extern __shared__ char smem[];
    Tf32Core g;
    int m0 = blockIdx.x * 128;            // in 6400
    int b  = blockIdx.y;
    g.init(smem_u32(smem), threadIdx.x,
           g_t + (size_t)b * 6400 * DDIM + (size_t)m0 * DDIM,
           g_e2t + (size_t)b * 128 * DDIM);
    g.run();

    float* dst = g_btp + (size_t)b * 6400 * 128;
    #pragma unroll
    for (int mt = 0; mt < 2; mt++) {
        int row = m0 + g.wm + mt * 16 + (g.lane >> 2);
        float* r0p = dst + (size_t)row * 128 + g.wn;
        float* r1p = r0p + 8 * 128;
        #pragma unroll
        for (int nt = 0; nt < 8; nt++) {
            int coff = nt * 8 + 2 * (g.lane & 3);
            *reinterpret_cast<float2*>(r0p + coff) = make_float2(g.acc[mt][nt][0], g.acc[mt][nt][1]);
            *reinterpret_cast<float2*>(r1p + coff) = make_float2(g.acc[mt][nt][2], g.acc[mt][nt][3]);
        }
    }
}

// ---------------------------------------------------------------------------
// gate epilogue: out[b,i,j] = sum_k u_k*( g*btp + (1-g)*tanh(sd) + bb_k )
// ---------------------------------------------------------------------------
#define G_P2LD 129
#define G_SMEM ((2 * KDIM * G_P2LD + 5 * 64) * 4)

__global__ __launch_bounds__(128)
void gate_kernel(const float* __restrict__ bg,
                 const float* __restrict__ bb,
                 const float* __restrict__ u,
                 float* __restrict__ out) {
    extern __shared__ float sm[];
    float* p2dS = sm;
    float* p2gS = sm + KDIM * G_P2LD;
    float* p1dS = p2gS + KDIM * G_P2LD;
    float* p1gS = p1dS + 64;
    float* uS   = p1gS + 64;
    float* bgS  = uS + 64;
    float* bbS  = bgS + 64;

    int blk = blockIdx.x;                 // b*128 + i
    int b   = blk >> 7;
    int tid = threadIdx.x;                // j

    const float* p2d_b = g_p2d + (size_t)b * 128 * KDIM;
    const float* p2g_b = g_p2g + (size_t)b * 128 * KDIM;
    for (int idx = tid; idx < 128 * KDIM; idx += 128) {
        int j = idx / KDIM, k = idx - j * KDIM;
        p2dS[k * G_P2LD + j] = p2d_b[idx];
        p2gS[k * G_P2LD + j] = p2g_b[idx];
    }
    if (tid < KDIM) {
        p1dS[tid] = g_p1d[(size_t)blk * KDIM + tid];
        p1gS[tid] = g_p1g[(size_t)blk * KDIM + tid];
        uS[tid]   = u[tid];
        bgS[tid]  = bg[tid];
        bbS[tid]  = bb[tid];
    }
    __syncthreads();

    const float* btp_row = g_btp + (size_t)b * 6400 * 128 + (size_t)(blk & 127) * KDIM * 128;

    float acc = 0.f;
    #pragma unroll 5
    for (int k = 0; k < KDIM; k++) {
        float btp = btp_row[k * 128 + tid];
        float sd  = p1dS[k] + p2dS[k * G_P2LD + tid];
        float sg  = p1gS[k] + p2gS[k * G_P2LD + tid] + bgS[k];
        float e   = __expf(-sg);
        float g   = __fdividef(1.f, 1.f + e);
        float sln = tanh_hw(sd);
        float mix = fmaf(g, btp - sln, sln) + bbS[k];
        acc = fmaf(uS[k], mix, acc);
    }
    out[(size_t)blk * 128 + tid] = acc;
}

// ---------------------------------------------------------------------------
// projections: warp = one 4-row group, lanes = consecutive k.
// ---------------------------------------------------------------------------
#define P_ROWS 32
#define P_THREADS 512
#define P_SMEM ((DDIM * KDIM + DDIM * P_ROWS) * 4)

__global__ __launch_bounds__(P_THREADS)
void proj_kernel(const float* __restrict__ e1,
                 const float* __restrict__ e2,
                 const float* __restrict__ Wd,
                 const float* __restrict__ Wg) {
    extern __shared__ float sm[];
    float* WS   = sm;                    // [300][50]
    float* rowS = sm + DDIM * KDIM;      // [300][32]

    int blk = blockIdx.x;
    int rt  = blk & 127;
    int mt  = (blk >> 7) & 1;
    int s   = blk >> 8;
    int row0 = rt * P_ROWS;
    int tid = threadIdx.x;

    const float* E = s ? e2 : e1;
    const float* W = (mt ? Wg : Wd) + s * DDIM * KDIM;
    float* out = s ? (mt ? g_p2g : g_p2d) : (mt ? g_p1g : g_p1d);

    const float4* W4 = reinterpret_cast<const float4*>(W);
    float4* WS4 = reinterpret_cast<float4*>(WS);
    for (int i = tid; i < DDIM * KDIM / 4; i += P_THREADS) WS4[i] = W4[i];

    for (int i = tid; i < P_ROWS * (DDIM / 4); i += P_THREADS) {
        int r = i / (DDIM / 4);
        int c4 = i % (DDIM / 4);
        float4 v = *reinterpret_cast<const float4*>(&E[(size_t)(row0 + r) * DDIM + 4 * c4]);
        rowS[(4 * c4 + 0) * P_ROWS + r] = v.x;
        rowS[(4 * c4 + 1) * P_ROWS + r] = v.y;
        rowS[(4 * c4 + 2) * P_ROWS + r] = v.z;
        rowS[(4 * c4 + 3) * P_ROWS + r] = v.w;
    }
    __syncthreads();

    int k  = tid & 63;
    int r4 = tid >> 6;                   // 0..7
    if (k < KDIM) {
        float4 acc = make_float4(0.f, 0.f, 0.f, 0.f);
        #pragma unroll 4
        for (int d = 0; d < DDIM; d++) {
            float4 x = *reinterpret_cast<const float4*>(&rowS[d * P_ROWS + r4 * 4]);
            float w = WS[d * KDIM + k];
            acc.x = fmaf(x.x, w, acc.x);
            acc.y = fmaf(x.y, w, acc.y);
            acc.z = fmaf(x.z, w, acc.z);
            acc.w = fmaf(x.w, w, acc.w);
        }
        int rb = row0 + r4 * 4;
        out[(size_t)(rb + 0) * KDIM + k] = acc.x;
        out[(size_t)(rb + 1) * KDIM + k] = acc.y;
        out[(size_t)(rb + 2) * KDIM + k] = acc.z;
        out[(size_t)(rb + 3) * KDIM + k] = acc.w;
    }
}

// ---------------------------------------------------------------------------
extern "C" void kernel_launch(void* const* d_in, const int* in_sizes, int n_in,
                              void* d_out, int out_size) {
    const float* e1 = (const float*)d_in[0];
    const float* e2 = (const float*)d_in[1];
    const float* Wb = (const float*)d_in[2];
    const float* Wd = (const float*)d_in[3];
    const float* Wg = (const float*)d_in[4];
    const float* bg = (const float*)d_in[5];
    const float* bb = (const float*)d_in[6];
    const float* u  = (const float*)d_in[7];
    float* out = (float*)d_out;

    cudaFuncSetAttribute(proj_kernel, cudaFuncAttributeMaxDynamicSharedMemorySize, P_SMEM);
    cudaFuncSetAttribute(tmat_tf32_kernel, cudaFuncAttributeMaxDynamicSharedMemorySize, BT_SMEM);
    cudaFuncSetAttribute(btp_tf32_kernel, cudaFuncAttributeMaxDynamicSharedMemorySize, BT_SMEM);
    cudaFuncSetAttribute(gate_kernel, cudaFuncAttributeMaxDynamicSharedMemorySize, G_SMEM);

    convE_kernel<<<2 * ROWS1, 320>>>(e1, e2);
    convB_kernel<<<dim3(10, 10, KDIM), dim3(32, 8)>>>(Wb);
    proj_kernel<<<512, P_THREADS, P_SMEM>>>(e1, e2, Wd, Wg);
    tmat_tf32_kernel<<<dim3(ROWS1 / 128, NPAD / 128), BT_THREADS, BT_SMEM>>>();
    btp_tf32_kernel<<<dim3(6400 / 128, BDIM), BT_THREADS, BT_SMEM>>>();
    gate_kernel<<<ROWS1, 128, G_SMEM>>>(bg, bb, u, out);
}

// round 14
// speedup vs baseline: 1.4794x; 1.0625x over previous
#include <cuda_runtime.h>
#include <cuda_bf16.h>
#include <math.h>
#include <stdint.h>

#define BDIM 32
#define L1DIM 128
#define L2DIM 128
#define DDIM 300
#define KDIM 50
#define ROWS1 (BDIM * L1DIM)   // 4096
#define ROWS2 (BDIM * L2DIM)   // 4096
#define NPAD 15104             // 118*128 compact (k*300+e) rows for Wb'
#define TSTRIDE (KDIM * DDIM)  // 15000

// Scratch (__device__ globals; zero-initialized at module load)
__device__ float g_t[(size_t)ROWS1 * TSTRIDE];           // 245.8 MB tf32-rounded t
__device__ float g_btp[(size_t)BDIM * 6400 * 128];       // 104.9 MB
__device__ float g_wbt[(size_t)NPAD * DDIM];             // 18.1 MB tf32 Wb'[(k*300+e)][d]
__device__ float g_e1t[(size_t)ROWS1 * DDIM];            // 4.9 MB tf32 e1
__device__ float g_e2t[(size_t)ROWS2 * DDIM];            // 4.9 MB tf32 e2
__device__ float g_p1d[ROWS1 * KDIM];
__device__ float g_p1g[ROWS1 * KDIM];
__device__ float g_p2d[ROWS2 * KDIM];
__device__ float g_p2g[ROWS2 * KDIM];

// ---------------------------------------------------------------------------
// helpers (plain sm_80+ PTX)
// ---------------------------------------------------------------------------
__device__ __forceinline__ uint32_t smem_u32(const void* p) {
    uint32_t a;
    asm("{ .reg .u64 t; cvta.to.shared.u64 t, %1; cvt.u32.u64 %0, t; }" : "=r"(a) : "l"(p));
    return a;
}
__device__ __forceinline__ void cpasync16z(uint32_t dst, const void* src, int nb) {
    asm volatile("cp.async.cg.shared.global [%0], [%1], 16, %2;"
                 :: "r"(dst), "l"(src), "r"(nb));
}
__device__ __forceinline__ void ldsm_x4(uint32_t& r0, uint32_t& r1, uint32_t& r2,
                                        uint32_t& r3, uint32_t addr) {
    asm volatile("ldmatrix.sync.aligned.m8n8.x4.shared.b16 {%0,%1,%2,%3}, [%4];"
                 : "=r"(r0), "=r"(r1), "=r"(r2), "=r"(r3) : "r"(addr));
}
__device__ __forceinline__ void mma_tf32(float* c, const uint32_t* a, const uint32_t* b) {
    asm volatile(
        "mma.sync.aligned.m16n8k8.row.col.f32.tf32.tf32.f32 "
        "{%0,%1,%2,%3}, {%4,%5,%6,%7}, {%8,%9}, {%0,%1,%2,%3};"
        : "+f"(c[0]), "+f"(c[1]), "+f"(c[2]), "+f"(c[3])
        : "r"(a[0]), "r"(a[1]), "r"(a[2]), "r"(a[3]), "r"(b[0]), "r"(b[1]));
}
__device__ __forceinline__ uint32_t f2tf32(float f) {
    uint32_t r;
    asm("cvt.rna.tf32.f32 %0, %1;" : "=r"(r) : "f"(f));
    return r;
}
__device__ __forceinline__ float tf32r(float f) {
    return __uint_as_float(f2tf32(f));
}
__device__ __forceinline__ float tanh_hw(float x) {
    float y;
    asm("tanh.approx.f32 %0, %1;" : "=f"(y) : "f"(x));
    return y;
}

// ---------------------------------------------------------------------------
// convE: e1/e2 fp32 -> tf32-rounded fp32 copies
// ---------------------------------------------------------------------------
__global__ void convE_kernel(const float* __restrict__ e1,
                             const float* __restrict__ e2) {
    int m = blockIdx.x;                  // 0..8191
    int d = threadIdx.x;                 // 0..319
    if (d >= DDIM) return;
    bool s2 = (m >= ROWS1);
    int row = s2 ? m - ROWS1 : m;
    const float* src = s2 ? e2 : e1;
    float* dst = s2 ? g_e2t : g_e1t;
    dst[(size_t)row * DDIM + d] = tf32r(src[(size_t)row * DDIM + d]);
}

// ---------------------------------------------------------------------------
// convB: Wb[k][d][e] -> tf32-rounded Wb'[(k*300+e)][d]
// ---------------------------------------------------------------------------
__global__ void convB_kernel(const float* __restrict__ Wb) {
    __shared__ float tile[32][33];
    int k  = blockIdx.z;
    int d0 = blockIdx.x * 32;
    int e0 = blockIdx.y * 32;
    int tx = threadIdx.x, ty = threadIdx.y;   // 32 x 8
    #pragma unroll
    for (int q = 0; q < 4; q++) {
        int d = d0 + ty + 8 * q;
        int e = e0 + tx;
        float v = 0.f;
        if (d < DDIM && e < DDIM)
            v = Wb[(size_t)k * DDIM * DDIM + (size_t)d * DDIM + e];
        tile[ty + 8 * q][tx] = v;
    }
    __syncthreads();
    #pragma unroll
    for (int q = 0; q < 4; q++) {
        int e = e0 + ty + 8 * q;
        int d = d0 + tx;
        if (e < DDIM && d < DDIM)
            g_wbt[(size_t)(k * DDIM + e) * DDIM + d] = tf32r(tile[tx][ty + 8 * q]);
    }
}

// ---------------------------------------------------------------------------
// tf32 GEMM core: CTA 128x128, 8 warps 4(m)x2(n) -> warp 32x64, KC=32,
// 2-stage cp.async, fp32 smem tiles, fragments via ldmatrix.x4 (tf32 elements
// = 4B lanes of 8x16B matrices; 144B row stride is conflict-free).
// 72 KB smem, 2 CTAs/SM.
// ---------------------------------------------------------------------------
#define BT_THREADS 256
#define BT_KC 32
#define BT_ROWB 144                       // 32 fp32 (128B) + 16B pad
#define BT_TILE (128 * BT_ROWB)           // 18432
#define BT_STAGE (2 * BT_TILE)            // A + B = 36864
#define BT_SMEM (2 * BT_STAGE)            // 73728
#define BT_NCH 10                         // ceil(300/32) (tail zero-filled)

struct Tf32Core {
    uint32_t sb;
    int tid, lane, wm, wn;
    const float *A, *B;
    float acc[2][8][4];

    __device__ __forceinline__ void init(uint32_t sb_, int tid_,
                                         const float* A_, const float* B_) {
        sb = sb_; tid = tid_;
        lane = tid & 31;
        int w = tid >> 5;
        wm = (w >> 1) * 32;               // 0,32,64,96
        wn = (w & 1) * 64;                // 0,64
        A = A_; B = B_;
        #pragma unroll
        for (int mt = 0; mt < 2; mt++)
            #pragma unroll
            for (int nt = 0; nt < 8; nt++)
                #pragma unroll
                for (int q = 0; q < 4; q++) acc[mt][nt][q] = 0.f;
    }

    __device__ __forceinline__ void issue(int c) {
        int d0 = c * BT_KC;
        uint32_t stage = sb + (c & 1) * BT_STAGE;
        #pragma unroll
        for (int it = 0; it < 8; it++) {
            int i = tid + BT_THREADS * it;        // 0..2047
            bool isA = (i < 1024);
            int idx = i & 1023;
            int r = idx >> 3, c4 = idx & 7;       // 128 rows x 8 float4
            int colb = d0 + c4 * 4;
            int nb = (colb + 4 <= DDIM) ? 16 : 0; // K tail: zero-fill
            const float* src = (isA ? A : B) + (size_t)r * DDIM + (nb ? colb : 0);
            uint32_t dst = stage + (isA ? 0 : BT_TILE) + r * BT_ROWB + c4 * 16;
            cpasync16z(dst, src, nb);
        }
        asm volatile("cp.async.commit_group;" ::: "memory");
    }

    __device__ __forceinline__ void compute(int c) {
        uint32_t sA = sb + (c & 1) * BT_STAGE;
        uint32_t sB = sA + BT_TILE;
        #pragma unroll
        for (int kk = 0; kk < BT_KC / 8; kk++) {
            // A fragments: 1 ldmatrix.x4 per mt
            // lanes 0-7: rows 0-7 (k lo), 8-15: rows 8-15 (k lo),
            // 16-23: rows 0-7 (k hi +16B), 24-31: rows 8-15 (k hi)
            uint32_t afr[2][4];
            #pragma unroll
            for (int mt = 0; mt < 2; mt++) {
                uint32_t aoff = (uint32_t)(wm + mt * 16 + (lane & 15)) * BT_ROWB
                              + kk * 32 + (lane >> 4) * 16;
                ldsm_x4(afr[mt][0], afr[mt][1], afr[mt][2], afr[mt][3], sA + aoff);
            }
            // B fragments: 1 ldmatrix.x4 per nt-pair
            // r0 = (nt=2q, k lo), r1 = (nt=2q, k hi), r2 = (2q+1, lo), r3 = (2q+1, hi)
            uint32_t bfr[8][2];
            #pragma unroll
            for (int nq = 0; nq < 4; nq++) {
                uint32_t brow = (uint32_t)(wn + nq * 16 + (lane & 7) + ((lane >> 4) << 3));
                uint32_t boff = brow * BT_ROWB + kk * 32 + ((lane >> 3) & 1) * 16;
                ldsm_x4(bfr[2*nq][0], bfr[2*nq][1], bfr[2*nq+1][0], bfr[2*nq+1][1], sB + boff);
            }
            #pragma unroll
            for (int mt = 0; mt < 2; mt++)
                #pragma unroll
                for (int nt = 0; nt < 8; nt++)
                    mma_tf32(acc[mt][nt], afr[mt], bfr[nt]);
        }
    }

    __device__ __forceinline__ void run() {
        issue(0);
        issue(1);
        for (int c = 0; c < BT_NCH; c++) {
            if (c + 1 < BT_NCH) {
                asm volatile("cp.async.wait_group 1;" ::: "memory");
            } else {
                asm volatile("cp.async.wait_group 0;" ::: "memory");
            }
            __syncthreads();
            compute(c);
            __syncthreads();
            if (c + 2 < BT_NCH) issue(c + 2);
        }
    }
};

// ---------------------------------------------------------------------------
// Stage-1 (tf32): t[4096 x 15000] = e1t[4096 x 300] @ Wb'[15104 x 300]^T
// ---------------------------------------------------------------------------
__global__ __launch_bounds__(BT_THREADS, 2)
void tmat_tf32_kernel() {
    extern __shared__ char smem[];
    Tf32Core g;
    int m0 = blockIdx.x * 128;            // in 4096
    int n0 = blockIdx.y * 128;            // in 15104
    g.init(smem_u32(smem), threadIdx.x,
           g_e1t + (size_t)m0 * DDIM,
           g_wbt + (size_t)n0 * DDIM);
    g.run();

    #pragma unroll
    for (int mt = 0; mt < 2; mt++) {
        int row = m0 + g.wm + mt * 16 + (g.lane >> 2);
        float* r0p = g_t + (size_t)row * TSTRIDE;
        float* r1p = r0p + (size_t)8 * TSTRIDE;
        #pragma unroll
        for (int nt = 0; nt < 8; nt++) {
            int col = n0 + g.wn + nt * 8 + 2 * (g.lane & 3);
            if (col < TSTRIDE) {
                *reinterpret_cast<float2*>(r0p + col) =
                    make_float2(tf32r(g.acc[mt][nt][0]), tf32r(g.acc[mt][nt][1]));
                *reinterpret_cast<float2*>(r1p + col) =
                    make_float2(tf32r(g.acc[mt][nt][2]), tf32r(g.acc[mt][nt][3]));
            }
        }
    }
}

// ---------------------------------------------------------------------------
// Stage-2 (tf32, per b): btp[6400 x 128] = T_b[6400 x 300] @ e2t_b[128 x 300]^T
// ---------------------------------------------------------------------------
__global__ __launch_bounds__(BT_THREADS, 2)
void btp_tf32_kernel() {
    extern __shared__ char smem[];
    Tf32Core g;
    int m0 = blockIdx.x * 128;            // in 6400
    int b  = blockIdx.y;
    g.init(smem_u32(smem), threadIdx.x,
           g_t + (size_t)b * 6400 * DDIM + (size_t)m0 * DDIM,
           g_e2t + (size_t)b * 128 * DDIM);
    g.run();

    float* dst = g_btp + (size_t)b * 6400 * 128;
    #pragma unroll
    for (int mt = 0; mt < 2; mt++) {
        int row = m0 + g.wm + mt * 16 + (g.lane >> 2);
        float* r0p = dst + (size_t)row * 128 + g.wn;
        float* r1p = r0p + 8 * 128;
        #pragma unroll
        for (int nt = 0; nt < 8; nt++) {
            int coff = nt * 8 + 2 * (g.lane & 3);
            *reinterpret_cast<float2*>(r0p + coff) = make_float2(g.acc[mt][nt][0], g.acc[mt][nt][1]);
            *reinterpret_cast<float2*>(r1p + coff) = make_float2(g.acc[mt][nt][2], g.acc[mt][nt][3]);
        }
    }
}

// ---------------------------------------------------------------------------
// gate epilogue: out[b,i,j] = sum_k u_k*( g*btp + (1-g)*tanh(sd) + bb_k )
// ---------------------------------------------------------------------------
#define G_P2LD 129
#define G_SMEM ((2 * KDIM * G_P2LD + 5 * 64) * 4)

__global__ __launch_bounds__(128)
void gate_kernel(const float* __restrict__ bg,
                 const float* __restrict__ bb,
                 const float* __restrict__ u,
                 float* __restrict__ out) {
    extern __shared__ float sm[];
    float* p2dS = sm;
    float* p2gS = sm + KDIM * G_P2LD;
    float* p1dS = p2gS + KDIM * G_P2LD;
    float* p1gS = p1dS + 64;
    float* uS   = p1gS + 64;
    float* bgS  = uS + 64;
    float* bbS  = bgS + 64;

    int blk = blockIdx.x;                 // b*128 + i
    int b   = blk >> 7;
    int tid = threadIdx.x;                // j

    const float* p2d_b = g_p2d + (size_t)b * 128 * KDIM;
    const float* p2g_b = g_p2g + (size_t)b * 128 * KDIM;
    for (int idx = tid; idx < 128 * KDIM; idx += 128) {
        int j = idx / KDIM, k = idx - j * KDIM;
        p2dS[k * G_P2LD + j] = p2d_b[idx];
        p2gS[k * G_P2LD + j] = p2g_b[idx];
    }
    if (tid < KDIM) {
        p1dS[tid] = g_p1d[(size_t)blk * KDIM + tid];
        p1gS[tid] = g_p1g[(size_t)blk * KDIM + tid];
        uS[tid]   = u[tid];
        bgS[tid]  = bg[tid];
        bbS[tid]  = bb[tid];
    }
    __syncthreads();

    const float* btp_row = g_btp + (size_t)b * 6400 * 128 + (size_t)(blk & 127) * KDIM * 128;

    float acc = 0.f;
    #pragma unroll 5
    for (int k = 0; k < KDIM; k++) {
        float btp = btp_row[k * 128 + tid];
        float sd  = p1dS[k] + p2dS[k * G_P2LD + tid];
        float sg  = p1gS[k] + p2gS[k * G_P2LD + tid] + bgS[k];
        float e   = __expf(-sg);
        float g   = __fdividef(1.f, 1.f + e);
        float sln = tanh_hw(sd);
        float mix = fmaf(g, btp - sln, sln) + bbS[k];
        acc = fmaf(uS[k], mix, acc);
    }
    out[(size_t)blk * 128 + tid] = acc;
}

// ---------------------------------------------------------------------------
// projections: warp = one 4-row group, lanes = consecutive k.
// ---------------------------------------------------------------------------
#define P_ROWS 32
#define P_THREADS 512
#define P_SMEM ((DDIM * KDIM + DDIM * P_ROWS) * 4)

__global__ __launch_bounds__(P_THREADS)
void proj_kernel(const float* __restrict__ e1,
                 const float* __restrict__ e2,
                 const float* __restrict__ Wd,
                 const float* __restrict__ Wg) {
    extern __shared__ float sm[];
    float* WS   = sm;                    // [300][50]
    float* rowS = sm + DDIM * KDIM;      // [300][32]

    int blk = blockIdx.x;
    int rt  = blk & 127;
    int mt  = (blk >> 7) & 1;
    int s   = blk >> 8;
    int row0 = rt * P_ROWS;
    int tid = threadIdx.x;

    const float* E = s ? e2 : e1;
    const float* W = (mt ? Wg : Wd) + s * DDIM * KDIM;
    float* out = s ? (mt ? g_p2g : g_p2d) : (mt ? g_p1g : g_p1d);

    const float4* W4 = reinterpret_cast<const float4*>(W);
    float4* WS4 = reinterpret_cast<float4*>(WS);
    for (int i = tid; i < DDIM * KDIM / 4; i += P_THREADS) WS4[i] = W4[i];

    for (int i = tid; i < P_ROWS * (DDIM / 4); i += P_THREADS) {
        int r = i / (DDIM / 4);
        int c4 = i % (DDIM / 4);
        float4 v = *reinterpret_cast<const float4*>(&E[(size_t)(row0 + r) * DDIM + 4 * c4]);
        rowS[(4 * c4 + 0) * P_ROWS + r] = v.x;
        rowS[(4 * c4 + 1) * P_ROWS + r] = v.y;
        rowS[(4 * c4 + 2) * P_ROWS + r] = v.z;
        rowS[(4 * c4 + 3) * P_ROWS + r] = v.w;
    }
    __syncthreads();

    int k  = tid & 63;
    int r4 = tid >> 6;                   // 0..7
    if (k < KDIM) {
        float4 acc = make_float4(0.f, 0.f, 0.f, 0.f);
        #pragma unroll 4
        for (int d = 0; d < DDIM; d++) {
            float4 x = *reinterpret_cast<const float4*>(&rowS[d * P_ROWS + r4 * 4]);
            float w = WS[d * KDIM + k];
            acc.x = fmaf(x.x, w, acc.x);
            acc.y = fmaf(x.y, w, acc.y);
            acc.z = fmaf(x.z, w, acc.z);
            acc.w = fmaf(x.w, w, acc.w);
        }
        int rb = row0 + r4 * 4;
        out[(size_t)(rb + 0) * KDIM + k] = acc.x;
        out[(size_t)(rb + 1) * KDIM + k] = acc.y;
        out[(size_t)(rb + 2) * KDIM + k] = acc.z;
        out[(size_t)(rb + 3) * KDIM + k] = acc.w;
    }
}

// ---------------------------------------------------------------------------
extern "C" void kernel_launch(void* const* d_in, const int* in_sizes, int n_in,
                              void* d_out, int out_size) {
    const float* e1 = (const float*)d_in[0];
    const float* e2 = (const float*)d_in[1];
    const float* Wb = (const float*)d_in[2];
    const float* Wd = (const float*)d_in[3];
    const float* Wg = (const float*)d_in[4];
    const float* bg = (const float*)d_in[5];
    const float* bb = (const float*)d_in[6];
    const float* u  = (const float*)d_in[7];
    float* out = (float*)d_out;

    cudaFuncSetAttribute(proj_kernel, cudaFuncAttributeMaxDynamicSharedMemorySize, P_SMEM);
    cudaFuncSetAttribute(tmat_tf32_kernel, cudaFuncAttributeMaxDynamicSharedMemorySize, BT_SMEM);
    cudaFuncSetAttribute(btp_tf32_kernel, cudaFuncAttributeMaxDynamicSharedMemorySize, BT_SMEM);
    cudaFuncSetAttribute(gate_kernel, cudaFuncAttributeMaxDynamicSharedMemorySize, G_SMEM);

    convE_kernel<<<2 * ROWS1, 320>>>(e1, e2);
    convB_kernel<<<dim3(10, 10, KDIM), dim3(32, 8)>>>(Wb);
    proj_kernel<<<512, P_THREADS, P_SMEM>>>(e1, e2, Wd, Wg);
    tmat_tf32_kernel<<<dim3(ROWS1 / 128, NPAD / 128), BT_THREADS, BT_SMEM>>>();
    btp_tf32_kernel<<<dim3(6400 / 128, BDIM), BT_THREADS, BT_SMEM>>>();
    gate_kernel<<<ROWS1, 128, G_SMEM>>>(bg, bb, u, out);
}

// round 15
// speedup vs baseline: 1.5418x; 1.0422x over previous
#include <cuda_runtime.h>
#include <cuda_bf16.h>
#include <math.h>
#include <stdint.h>

#define BDIM 32
#define L1DIM 128
#define L2DIM 128
#define DDIM 300
#define KDIM 50
#define ROWS1 (BDIM * L1DIM)   // 4096
#define ROWS2 (BDIM * L2DIM)   // 4096
#define NPAD 15104             // 118*128 compact (k*300+e) rows for Wb'
#define TSTRIDE (KDIM * DDIM)  // 15000

// Scratch (__device__ globals; zero-initialized at module load)
__device__ float g_t[(size_t)ROWS1 * TSTRIDE];           // 245.8 MB tf32-rounded t
__device__ float g_btp[(size_t)BDIM * 6400 * 128];       // 104.9 MB
__device__ float g_wbt[(size_t)NPAD * DDIM];             // 18.1 MB tf32 Wb'[(k*300+e)][d]
__device__ float g_e1t[(size_t)ROWS1 * DDIM];            // 4.9 MB tf32 e1
__device__ float g_e2t[(size_t)ROWS2 * DDIM];            // 4.9 MB tf32 e2
__device__ float g_p1d[ROWS1 * KDIM];
__device__ float g_p1g[ROWS1 * KDIM];
__device__ float g_p2d[ROWS2 * KDIM];
__device__ float g_p2g[ROWS2 * KDIM];

// ---------------------------------------------------------------------------
// helpers (plain sm_80+ PTX)
// ---------------------------------------------------------------------------
__device__ __forceinline__ uint32_t smem_u32(const void* p) {
    uint32_t a;
    asm("{ .reg .u64 t; cvta.to.shared.u64 t, %1; cvt.u32.u64 %0, t; }" : "=r"(a) : "l"(p));
    return a;
}
__device__ __forceinline__ void cpasync16z(uint32_t dst, const void* src, int nb) {
    asm volatile("cp.async.cg.shared.global [%0], [%1], 16, %2;"
                 :: "r"(dst), "l"(src), "r"(nb));
}
__device__ __forceinline__ void ldsm_x4(uint32_t& r0, uint32_t& r1, uint32_t& r2,
                                        uint32_t& r3, uint32_t addr) {
    asm volatile("ldmatrix.sync.aligned.m8n8.x4.shared.b16 {%0,%1,%2,%3}, [%4];"
                 : "=r"(r0), "=r"(r1), "=r"(r2), "=r"(r3) : "r"(addr));
}
__device__ __forceinline__ void mma_tf32(float* c, const uint32_t* a, const uint32_t* b) {
    asm volatile(
        "mma.sync.aligned.m16n8k8.row.col.f32.tf32.tf32.f32 "
        "{%0,%1,%2,%3}, {%4,%5,%6,%7}, {%8,%9}, {%0,%1,%2,%3};"
        : "+f"(c[0]), "+f"(c[1]), "+f"(c[2]), "+f"(c[3])
        : "r"(a[0]), "r"(a[1]), "r"(a[2]), "r"(a[3]), "r"(b[0]), "r"(b[1]));
}
__device__ __forceinline__ uint32_t f2tf32(float f) {
    uint32_t r;
    asm("cvt.rna.tf32.f32 %0, %1;" : "=r"(r) : "f"(f));
    return r;
}
__device__ __forceinline__ float tf32r(float f) {
    return __uint_as_float(f2tf32(f));
}
__device__ __forceinline__ float tanh_hw(float x) {
    float y;
    asm("tanh.approx.f32 %0, %1;" : "=f"(y) : "f"(x));
    return y;
}

// ---------------------------------------------------------------------------
// convE: e1/e2 fp32 -> tf32-rounded fp32 copies
// ---------------------------------------------------------------------------
__global__ void convE_kernel(const float* __restrict__ e1,
                             const float* __restrict__ e2) {
    int m = blockIdx.x;                  // 0..8191
    int d = threadIdx.x;                 // 0..319
    if (d >= DDIM) return;
    bool s2 = (m >= ROWS1);
    int row = s2 ? m - ROWS1 : m;
    const float* src = s2 ? e2 : e1;
    float* dst = s2 ? g_e2t : g_e1t;
    dst[(size_t)row * DDIM + d] = tf32r(src[(size_t)row * DDIM + d]);
}

// ---------------------------------------------------------------------------
// convB: Wb[k][d][e] -> tf32-rounded Wb'[(k*300+e)][d]
// ---------------------------------------------------------------------------
__global__ void convB_kernel(const float* __restrict__ Wb) {
    __shared__ float tile[32][33];
    int k  = blockIdx.z;
    int d0 = blockIdx.x * 32;
    int e0 = blockIdx.y * 32;
    int tx = threadIdx.x, ty = threadIdx.y;   // 32 x 8
    #pragma unroll
    for (int q = 0; q < 4; q++) {
        int d = d0 + ty + 8 * q;
        int e = e0 + tx;
        float v = 0.f;
        if (d < DDIM && e < DDIM)
            v = Wb[(size_t)k * DDIM * DDIM + (size_t)d * DDIM + e];
        tile[ty + 8 * q][tx] = v;
    }
    __syncthreads();
    #pragma unroll
    for (int q = 0; q < 4; q++) {
        int e = e0 + ty + 8 * q;
        int d = d0 + tx;
        if (e < DDIM && d < DDIM)
            g_wbt[(size_t)(k * DDIM + e) * DDIM + d] = tf32r(tile[tx][ty + 8 * q]);
    }
}

// ---------------------------------------------------------------------------
// tf32 GEMM core: CTA 128x128, 8 warps 4(m)x2(n) -> warp 32x64, KC=32,
// 3-stage cp.async ring with ONE syncthreads per chunk, fragments via
// ldmatrix.x4. 108 KB smem, 2 CTAs/SM.
// ---------------------------------------------------------------------------
#define BT_THREADS 256
#define BT_KC 32
#define BT_ROWB 144                       // 32 fp32 (128B) + 16B pad
#define BT_TILE (128 * BT_ROWB)           // 18432
#define BT_STAGE (2 * BT_TILE)            // A + B = 36864
#define BT_SMEM (3 * BT_STAGE)            // 110592 (3-stage ring)
#define BT_NCH 10                         // ceil(300/32) (tail zero-filled)

struct Tf32Core {
    uint32_t sb;
    int tid, lane, wm, wn;
    const float *A, *B;
    float acc[2][8][4];

    __device__ __forceinline__ void init(uint32_t sb_, int tid_,
                                         const float* A_, const float* B_) {
        sb = sb_; tid = tid_;
        lane = tid & 31;
        int w = tid >> 5;
        wm = (w >> 1) * 32;               // 0,32,64,96
        wn = (w & 1) * 64;                // 0,64
        A = A_; B = B_;
        #pragma unroll
        for (int mt = 0; mt < 2; mt++)
            #pragma unroll
            for (int nt = 0; nt < 8; nt++)
                #pragma unroll
                for (int q = 0; q < 4; q++) acc[mt][nt][q] = 0.f;
    }

    __device__ __forceinline__ void issue(int c) {
        int d0 = c * BT_KC;
        uint32_t stage = sb + (c % 3) * BT_STAGE;
        #pragma unroll
        for (int it = 0; it < 8; it++) {
            int i = tid + BT_THREADS * it;        // 0..2047
            bool isA = (i < 1024);
            int idx = i & 1023;
            int r = idx >> 3, c4 = idx & 7;       // 128 rows x 8 float4
            int colb = d0 + c4 * 4;
            int nb = (colb + 4 <= DDIM) ? 16 : 0; // K tail: zero-fill
            const float* src = (isA ? A : B) + (size_t)r * DDIM + (nb ? colb : 0);
            uint32_t dst = stage + (isA ? 0 : BT_TILE) + r * BT_ROWB + c4 * 16;
            cpasync16z(dst, src, nb);
        }
        asm volatile("cp.async.commit_group;" ::: "memory");
    }

    __device__ __forceinline__ void compute(int c) {
        uint32_t sA = sb + (c % 3) * BT_STAGE;
        uint32_t sB = sA + BT_TILE;
        #pragma unroll
        for (int kk = 0; kk < BT_KC / 8; kk++) {
            uint32_t afr[2][4];
            #pragma unroll
            for (int mt = 0; mt < 2; mt++) {
                uint32_t aoff = (uint32_t)(wm + mt * 16 + (lane & 15)) * BT_ROWB
                              + kk * 32 + (lane >> 4) * 16;
                ldsm_x4(afr[mt][0], afr[mt][1], afr[mt][2], afr[mt][3], sA + aoff);
            }
            uint32_t bfr[8][2];
            #pragma unroll
            for (int nq = 0; nq < 4; nq++) {
                uint32_t brow = (uint32_t)(wn + nq * 16 + (lane & 7) + ((lane >> 4) << 3));
                uint32_t boff = brow * BT_ROWB + kk * 32 + ((lane >> 3) & 1) * 16;
                ldsm_x4(bfr[2*nq][0], bfr[2*nq][1], bfr[2*nq+1][0], bfr[2*nq+1][1], sB + boff);
            }
            #pragma unroll
            for (int mt = 0; mt < 2; mt++)
                #pragma unroll
                for (int nt = 0; nt < 8; nt++)
                    mma_tf32(acc[mt][nt], afr[mt], bfr[nt]);
        }
    }

    // 3-stage ring: issue(c+2) overwrites stage (c-1)%3 whose readers finished
    // before this iteration's pre-compute sync -> ONE sync per chunk.
    __device__ __forceinline__ void run() {
        issue(0);
        issue(1);
        for (int c = 0; c < BT_NCH; c++) {
            if (c + 1 < BT_NCH) {
                asm volatile("cp.async.wait_group 1;" ::: "memory");
            } else {
                asm volatile("cp.async.wait_group 0;" ::: "memory");
            }
            __syncthreads();
            compute(c);
            if (c + 2 < BT_NCH) issue(c + 2);
        }
    }
};

// ---------------------------------------------------------------------------
// Stage-1 (tf32): t[4096 x 15000] = e1t[4096 x 300] @ Wb'[15104 x 300]^T
// ---------------------------------------------------------------------------
__global__ __launch_bounds__(BT_THREADS, 2)
void tmat_tf32_kernel() {
    extern __shared__ char smem[];
    Tf32Core g;
    int m0 = blockIdx.x * 128;            // in 4096
    int n0 = blockIdx.y * 128;            // in 15104
    g.init(smem_u32(smem), threadIdx.x,
           g_e1t + (size_t)m0 * DDIM,
           g_wbt + (size_t)n0 * DDIM);
    g.run();

    #pragma unroll
    for (int mt = 0; mt < 2; mt++) {
        int row = m0 + g.wm + mt * 16 + (g.lane >> 2);
        float* r0p = g_t + (size_t)row * TSTRIDE;
        float* r1p = r0p + (size_t)8 * TSTRIDE;
        #pragma unroll
        for (int nt = 0; nt < 8; nt++) {
            int col = n0 + g.wn + nt * 8 + 2 * (g.lane & 3);
            if (col < TSTRIDE) {
                *reinterpret_cast<float2*>(r0p + col) =
                    make_float2(tf32r(g.acc[mt][nt][0]), tf32r(g.acc[mt][nt][1]));
                *reinterpret_cast<float2*>(r1p + col) =
                    make_float2(tf32r(g.acc[mt][nt][2]), tf32r(g.acc[mt][nt][3]));
            }
        }
    }
}

// ---------------------------------------------------------------------------
// Stage-2 (tf32, per b): btp[6400 x 128] = T_b[6400 x 300] @ e2t_b[128 x 300]^T
// ---------------------------------------------------------------------------
__global__ __launch_bounds__(BT_THREADS, 2)
void btp_tf32_kernel() {
    extern __shared__ char smem[];
    Tf32Core g;
    int m0 = blockIdx.x * 128;            // in 6400
    int b  = blockIdx.y;
    g.init(smem_u32(smem), threadIdx.x,
           g_t + (size_t)b * 6400 * DDIM + (size_t)m0 * DDIM,
           g_e2t + (size_t)b * 128 * DDIM);
    g.run();

    float* dst = g_btp + (size_t)b * 6400 * 128;
    #pragma unroll
    for (int mt = 0; mt < 2; mt++) {
        int row = m0 + g.wm + mt * 16 + (g.lane >> 2);
        float* r0p = dst + (size_t)row * 128 + g.wn;
        float* r1p = r0p + 8 * 128;
        #pragma unroll
        for (int nt = 0; nt < 8; nt++) {
            int coff = nt * 8 + 2 * (g.lane & 3);
            *reinterpret_cast<float2*>(r0p + coff) = make_float2(g.acc[mt][nt][0], g.acc[mt][nt][1]);
            *reinterpret_cast<float2*>(r1p + coff) = make_float2(g.acc[mt][nt][2], g.acc[mt][nt][3]);
        }
    }
}

// ---------------------------------------------------------------------------
// gate epilogue: out[b,i,j] = sum_k u_k*( g*btp + (1-g)*tanh(sd) + bb_k )
// ---------------------------------------------------------------------------
#define G_P2LD 129
#define G_SMEM ((2 * KDIM * G_P2LD + 5 * 64) * 4)

__global__ __launch_bounds__(128)
void gate_kernel(const float* __restrict__ bg,
                 const float* __restrict__ bb,
                 const float* __restrict__ u,
                 float* __restrict__ out) {
    extern __shared__ float sm[];
    float* p2dS = sm;
    float* p2gS = sm + KDIM * G_P2LD;
    float* p1dS = p2gS + KDIM * G_P2LD;
    float* p1gS = p1dS + 64;
    float* uS   = p1gS + 64;
    float* bgS  = uS + 64;
    float* bbS  = bgS + 64;

    int blk = blockIdx.x;                 // b*128 + i
    int b   = blk >> 7;
    int tid = threadIdx.x;                // j

    const float* p2d_b = g_p2d + (size_t)b * 128 * KDIM;
    const float* p2g_b = g_p2g + (size_t)b * 128 * KDIM;
    for (int idx = tid; idx < 128 * KDIM; idx += 128) {
        int j = idx / KDIM, k = idx - j * KDIM;
        p2dS[k * G_P2LD + j] = p2d_b[idx];
        p2gS[k * G_P2LD + j] = p2g_b[idx];
    }
    if (tid < KDIM) {
        p1dS[tid] = g_p1d[(size_t)blk * KDIM + tid];
        p1gS[tid] = g_p1g[(size_t)blk * KDIM + tid];
        uS[tid]   = u[tid];
        bgS[tid]  = bg[tid];
        bbS[tid]  = bb[tid];
    }
    __syncthreads();

    const float* btp_row = g_btp + (size_t)b * 6400 * 128 + (size_t)(blk & 127) * KDIM * 128;

    float acc = 0.f;
    #pragma unroll 5
    for (int k = 0; k < KDIM; k++) {
        float btp = btp_row[k * 128 + tid];
        float sd  = p1dS[k] + p2dS[k * G_P2LD + tid];
        float sg  = p1gS[k] + p2gS[k * G_P2LD + tid] + bgS[k];
        float e   = __expf(-sg);
        float g   = __fdividef(1.f, 1.f + e);
        float sln = tanh_hw(sd);
        float mix = fmaf(g, btp - sln, sln) + bbS[k];
        acc = fmaf(uS[k], mix, acc);
    }
    out[(size_t)blk * 128 + tid] = acc;
}

// ---------------------------------------------------------------------------
// projections: warp = one 4-row group, lanes = consecutive k.
// ---------------------------------------------------------------------------
#define P_ROWS 32
#define P_THREADS 512
#define P_SMEM ((DDIM * KDIM + DDIM * P_ROWS) * 4)

__global__ __launch_bounds__(P_THREADS)
void proj_kernel(const float* __restrict__ e1,
                 const float* __restrict__ e2,
                 const float* __restrict__ Wd,
                 const float* __restrict__ Wg) {
    extern __shared__ float sm[];
    float* WS   = sm;                    // [300][50]
    float* rowS = sm + DDIM * KDIM;      // [300][32]

    int blk = blockIdx.x;
    int rt  = blk & 127;
    int mt  = (blk >> 7) & 1;
    int s   = blk >> 8;
    int row0 = rt * P_ROWS;
    int tid = threadIdx.x;

    const float* E = s ? e2 : e1;
    const float* W = (mt ? Wg : Wd) + s * DDIM * KDIM;
    float* out = s ? (mt ? g_p2g : g_p2d) : (mt ? g_p1g : g_p1d);

    const float4* W4 = reinterpret_cast<const float4*>(W);
    float4* WS4 = reinterpret_cast<float4*>(WS);
    for (int i = tid; i < DDIM * KDIM / 4; i += P_THREADS) WS4[i] = W4[i];

    for (int i = tid; i < P_ROWS * (DDIM / 4); i += P_THREADS) {
        int r = i / (DDIM / 4);
        int c4 = i % (DDIM / 4);
        float4 v = *reinterpret_cast<const float4*>(&E[(size_t)(row0 + r) * DDIM + 4 * c4]);
        rowS[(4 * c4 + 0) * P_ROWS + r] = v.x;
        rowS[(4 * c4 + 1) * P_ROWS + r] = v.y;
        rowS[(4 * c4 + 2) * P_ROWS + r] = v.z;
        rowS[(4 * c4 + 3) * P_ROWS + r] = v.w;
    }
    __syncthreads();

    int k  = tid & 63;
    int r4 = tid >> 6;                   // 0..7
    if (k < KDIM) {
        float4 acc = make_float4(0.f, 0.f, 0.f, 0.f);
        #pragma unroll 4
        for (int d = 0; d < DDIM; d++) {
            float4 x = *reinterpret_cast<const float4*>(&rowS[d * P_ROWS + r4 * 4]);
            float w = WS[d * KDIM + k];
            acc.x = fmaf(x.x, w, acc.x);
            acc.y = fmaf(x.y, w, acc.y);
            acc.z = fmaf(x.z, w, acc.z);
            acc.w = fmaf(x.w, w, acc.w);
        }
        int rb = row0 + r4 * 4;
        out[(size_t)(rb + 0) * KDIM + k] = acc.x;
        out[(size_t)(rb + 1) * KDIM + k] = acc.y;
        out[(size_t)(rb + 2) * KDIM + k] = acc.z;
        out[(size_t)(rb + 3) * KDIM + k] = acc.w;
    }
}

// ---------------------------------------------------------------------------
extern "C" void kernel_launch(void* const* d_in, const int* in_sizes, int n_in,
                              void* d_out, int out_size) {
    const float* e1 = (const float*)d_in[0];
    const float* e2 = (const float*)d_in[1];
    const float* Wb = (const float*)d_in[2];
    const float* Wd = (const float*)d_in[3];
    const float* Wg = (const float*)d_in[4];
    const float* bg = (const float*)d_in[5];
    const float* bb = (const float*)d_in[6];
    const float* u  = (const float*)d_in[7];
    float* out = (float*)d_out;

    cudaFuncSetAttribute(proj_kernel, cudaFuncAttributeMaxDynamicSharedMemorySize, P_SMEM);
    cudaFuncSetAttribute(tmat_tf32_kernel, cudaFuncAttributeMaxDynamicSharedMemorySize, BT_SMEM);
    cudaFuncSetAttribute(btp_tf32_kernel, cudaFuncAttributeMaxDynamicSharedMemorySize, BT_SMEM);
    cudaFuncSetAttribute(gate_kernel, cudaFuncAttributeMaxDynamicSharedMemorySize, G_SMEM);

    convE_kernel<<<2 * ROWS1, 320>>>(e1, e2);
    convB_kernel<<<dim3(10, 10, KDIM), dim3(32, 8)>>>(Wb);
    proj_kernel<<<512, P_THREADS, P_SMEM>>>(e1, e2, Wd, Wg);
    tmat_tf32_kernel<<<dim3(ROWS1 / 128, NPAD / 128), BT_THREADS, BT_SMEM>>>();
    btp_tf32_kernel<<<dim3(6400 / 128, BDIM), BT_THREADS, BT_SMEM>>>();
    gate_kernel<<<ROWS1, 128, G_SMEM>>>(bg, bb, u, out);
}